// round 3
// baseline (speedup 1.0000x reference)
#include <cuda_runtime.h>

#define F 128
#define NMAX 65536
#define EMAX 1200000

// ---------------- scratch (no allocations allowed) ----------------
__device__ float g_xp[NMAX * F];        // x @ W
__device__ float g_asrc[NMAX];          // xp @ att_src
__device__ float g_adst[NMAX];          // xp @ att_dst
__device__ int   g_hist[NMAX];          // in-degree (incl. self loop)
__device__ int   g_rowstart[NMAX + 1];  // CSR offsets by dst
__device__ int   g_cursor[NMAX];        // scatter cursors
__device__ int   g_srcsorted[EMAX];     // src ids grouped by dst
__device__ int   g_is64;                // 1 if edge_index is int64

// edge fetch that works for both int32 and int64 buffers
__device__ __forceinline__ int edge_at(const void* ei, int idx, int is64) {
    if (is64) return (int)((const long long*)ei)[idx];
    return ((const int*)ei)[idx];
}

// ---------------- 0) dtype detection ----------------
// If int64: every odd 32-bit word is the zero high-half (values < 2^31).
__global__ void k_detect(const int* __restrict__ ei32, int E) {
    __shared__ int any;
    if (threadIdx.x == 0) any = 0;
    __syncthreads();
    int total = 2 * E;
    int stride = (total / 2) / 4096;
    if (stride < 1) stride = 1;
    for (int q = threadIdx.x; q < 4096; q += blockDim.x) {
        long long w = 1 + 2 * (long long)q * stride;
        if (w < total && ei32[w] != 0) { any = 1; break; }
    }
    __syncthreads();
    if (threadIdx.x == 0) g_is64 = (any == 0) ? 1 : 0;
}

// ---------------- 1) GEMM: xp = x @ W  (fp32 SIMT, 64x128 tile) ----------------
__global__ void k_gemm(const float* __restrict__ x, const float* __restrict__ W, int N) {
    __shared__ float xs[64 * 128];  // 32 KB
    __shared__ float ws[32 * 128];  // 16 KB
    const int tid = threadIdx.x;       // 256 threads
    const int tx = tid & 15;
    const int ty = tid >> 4;
    const int row0 = blockIdx.x * 64;

    {   // load x tile
        float4* xs4 = (float4*)xs;
        const float4* x4 = (const float4*)x;
        #pragma unroll
        for (int q = 0; q < 8; ++q) {
            int fi = q * 256 + tid;
            int r = fi >> 5, c4 = fi & 31;
            int gr = row0 + r;
            float4 v = make_float4(0.f, 0.f, 0.f, 0.f);
            if (gr < N) v = x4[gr * 32 + c4];
            xs4[fi] = v;
        }
    }

    float acc[4][8];
    #pragma unroll
    for (int i = 0; i < 4; ++i)
        #pragma unroll
        for (int j = 0; j < 8; ++j) acc[i][j] = 0.f;

    for (int kt = 0; kt < 4; ++kt) {
        __syncthreads();
        {   // load W k-tile
            float4* ws4 = (float4*)ws;
            const float4* W4 = (const float4*)W;
            #pragma unroll
            for (int q = 0; q < 4; ++q) {
                int fi = q * 256 + tid;
                int r = fi >> 5, c4 = fi & 31;
                ws4[fi] = W4[(kt * 32 + r) * 32 + c4];
            }
        }
        __syncthreads();
        #pragma unroll
        for (int k = 0; k < 32; ++k) {
            float xv[4];
            #pragma unroll
            for (int i = 0; i < 4; ++i) xv[i] = xs[(ty * 4 + i) * 128 + kt * 32 + k];
            float4 wa = ((float4*)ws)[k * 32 + tx * 2];
            float4 wb = ((float4*)ws)[k * 32 + tx * 2 + 1];
            #pragma unroll
            for (int i = 0; i < 4; ++i) {
                acc[i][0] += xv[i] * wa.x; acc[i][1] += xv[i] * wa.y;
                acc[i][2] += xv[i] * wa.z; acc[i][3] += xv[i] * wa.w;
                acc[i][4] += xv[i] * wb.x; acc[i][5] += xv[i] * wb.y;
                acc[i][6] += xv[i] * wb.z; acc[i][7] += xv[i] * wb.w;
            }
        }
    }

    #pragma unroll
    for (int i = 0; i < 4; ++i) {
        int gr = row0 + ty * 4 + i;
        if (gr < N) {
            float4* o = (float4*)&g_xp[gr * 128 + tx * 8];
            o[0] = make_float4(acc[i][0], acc[i][1], acc[i][2], acc[i][3]);
            o[1] = make_float4(acc[i][4], acc[i][5], acc[i][6], acc[i][7]);
        }
    }
}

// ---------------- 2) per-node attention logits; seed hist with self-loop ----------------
__global__ void k_att(const float* __restrict__ att_src, const float* __restrict__ att_dst, int N) {
    int warp = (blockIdx.x * blockDim.x + threadIdx.x) >> 5;
    int lane = threadIdx.x & 31;
    if (warp >= N) return;
    float4 v  = ((const float4*)(g_xp + (size_t)warp * 128))[lane];
    float4 as = ((const float4*)att_src)[lane];
    float4 ad = ((const float4*)att_dst)[lane];
    float ds = v.x * as.x + v.y * as.y + v.z * as.z + v.w * as.w;
    float dd = v.x * ad.x + v.y * ad.y + v.z * ad.z + v.w * ad.w;
    #pragma unroll
    for (int o = 16; o > 0; o >>= 1) {
        ds += __shfl_xor_sync(0xffffffffu, ds, o);
        dd += __shfl_xor_sync(0xffffffffu, dd, o);
    }
    if (lane == 0) {
        g_asrc[warp] = ds;
        g_adst[warp] = dd;
        g_hist[warp] = 1;   // self loop
    }
}

// ---------------- 3) histogram of dst ----------------
__global__ void k_hist(const void* __restrict__ ei, int E) {
    int e = blockIdx.x * blockDim.x + threadIdx.x;
    if (e < E) {
        int d = edge_at(ei, E + e, g_is64);
        atomicAdd(&g_hist[d], 1);
    }
}

// ---------------- 4) single-block exclusive scan -> rowstart & cursor ----------------
__global__ void k_scan(int N) {
    __shared__ int sp[1024];
    int tid = threadIdx.x;
    int C = (N + 1023) >> 10;
    int b = tid * C;
    int e = min(b + C, N);
    int sum = 0;
    for (int i = b; i < e; ++i) sum += g_hist[i];
    sp[tid] = sum;
    __syncthreads();
    for (int off = 1; off < 1024; off <<= 1) {
        int v = (tid >= off) ? sp[tid - off] : 0;
        __syncthreads();
        sp[tid] += v;
        __syncthreads();
    }
    int run = (tid == 0) ? 0 : sp[tid - 1];
    for (int i = b; i < e; ++i) {
        int h = g_hist[i];
        g_rowstart[i] = run;
        g_cursor[i]   = run;
        run += h;
    }
    if (tid == 1023) g_rowstart[N] = sp[1023];
}

// ---------------- 5) scatter edges (and self loops) into dst-grouped order ----------------
__global__ void k_scatter(const void* __restrict__ ei, int N, int E) {
    int idx = blockIdx.x * blockDim.x + threadIdx.x;
    int is64 = g_is64;
    if (idx < E) {
        int d = edge_at(ei, E + idx, is64);
        int s = edge_at(ei, idx, is64);
        int pos = atomicAdd(&g_cursor[d], 1);
        g_srcsorted[pos] = s;
    } else if (idx < E + N) {
        int i = idx - E;
        int pos = atomicAdd(&g_cursor[i], 1);
        g_srcsorted[pos] = i;   // self loop
    }
}

// ---------------- 6) fused segment softmax + weighted aggregation ----------------
// one block (128 threads) per destination node; thread = feature channel
__global__ void k_agg(const float* __restrict__ bias, float* __restrict__ out, int N) {
    const int d = blockIdx.x;
    const int tid = threadIdx.x;
    __shared__ float sred[128];
    __shared__ float w_s[128];
    __shared__ int   s_s[128];

    const int beg = g_rowstart[d];
    const int end = g_rowstart[d + 1];
    const float adst = g_adst[d];

    // phase A: segment max
    float m = -3.4e38f;
    for (int j = beg + tid; j < end; j += 128) {
        float e = g_asrc[g_srcsorted[j]] + adst;
        e = (e >= 0.f) ? e : 0.2f * e;
        m = fmaxf(m, e);
    }
    sred[tid] = m;
    __syncthreads();
    for (int s = 64; s > 0; s >>= 1) {
        if (tid < s) sred[tid] = fmaxf(sred[tid], sred[tid + s]);
        __syncthreads();
    }
    m = sred[0];
    __syncthreads();

    // phase B: denominator
    float ssum = 0.f;
    for (int j = beg + tid; j < end; j += 128) {
        float e = g_asrc[g_srcsorted[j]] + adst;
        e = (e >= 0.f) ? e : 0.2f * e;
        ssum += __expf(e - m);
    }
    sred[tid] = ssum;
    __syncthreads();
    for (int s = 64; s > 0; s >>= 1) {
        if (tid < s) sred[tid] += sred[tid + s];
        __syncthreads();
    }
    const float inv = 1.f / sred[0];

    // phase C: weighted feature aggregation, exp once per edge, 2-way MLP
    float acc0 = 0.f, acc1 = 0.f;
    for (int base = beg; base < end; base += 128) {
        __syncthreads();
        int j = base + tid;
        if (j < end) {
            int s = g_srcsorted[j];
            float e = g_asrc[s] + adst;
            e = (e >= 0.f) ? e : 0.2f * e;
            s_s[tid] = s;
            w_s[tid] = __expf(e - m);
        }
        __syncthreads();
        int cnt = min(128, end - base);
        int jj = 0;
        for (; jj + 1 < cnt; jj += 2) {
            float v0 = g_xp[(size_t)s_s[jj]     * 128 + tid];
            float v1 = g_xp[(size_t)s_s[jj + 1] * 128 + tid];
            acc0 += w_s[jj] * v0;
            acc1 += w_s[jj + 1] * v1;
        }
        if (jj < cnt) acc0 += w_s[jj] * g_xp[(size_t)s_s[jj] * 128 + tid];
    }
    out[(size_t)d * 128 + tid] = (acc0 + acc1) * inv + bias[tid];
}

// ---------------- launch ----------------
extern "C" void kernel_launch(void* const* d_in, const int* in_sizes, int n_in,
                              void* d_out, int out_size) {
    const float* x        = (const float*)d_in[0];
    const float* W        = (const float*)d_in[1];
    const float* att_src  = (const float*)d_in[2];
    const float* att_dst  = (const float*)d_in[3];
    const float* bias     = (const float*)d_in[4];
    const void*  ei       = d_in[5];   // [2, E] int32 or int64 (detected on device)

    const int N = in_sizes[0] / F;
    const int E = in_sizes[5] / 2;
    float* out = (float*)d_out;

    k_detect <<<1, 256>>>((const int*)ei, E);
    k_gemm   <<<(N + 63) / 64, 256>>>(x, W, N);
    k_att    <<<(N + 7) / 8, 256>>>(att_src, att_dst, N);
    k_hist   <<<(E + 255) / 256, 256>>>(ei, E);
    k_scan   <<<1, 1024>>>(N);
    k_scatter<<<(E + N + 255) / 256, 256>>>(ei, N, E);
    k_agg    <<<N, 128>>>(bias, out, N);
}

// round 5
// speedup vs baseline: 1.2295x; 1.2295x over previous
#include <cuda_runtime.h>

#define F 128
#define NMAX 65536
#define EMAX 1200000

// ---------------- scratch (no allocations allowed) ----------------
__device__ float    g_xp[NMAX * F];        // x @ W
__device__ float    g_asrc[NMAX];          // xp @ att_src
__device__ float    g_adst[NMAX];          // xp @ att_dst
__device__ int      g_hist[NMAX];          // in-degree (incl. self loop)
__device__ int      g_rowstart[NMAX + 1];  // CSR offsets by dst
__device__ int      g_cursor[NMAX];        // scatter cursors
__device__ int2     g_edge[EMAX];          // (src, logit-bits) grouped by dst
__device__ float    g_wsorted[EMAX];       // exp(e - m), dst-grouped
__device__ unsigned g_maxkey[NMAX];        // ordered-uint encoding of segment max
__device__ float    g_inv[NMAX];           // 1 / sum(exp)
__device__ int      g_is64;                // 1 if edge_index is int64

__device__ __forceinline__ int edge_at(const void* ei, int idx, int is64) {
    if (is64) return (int)((const long long*)ei)[idx];
    return ((const int*)ei)[idx];
}

// monotone float -> uint key (for atomicMax on possibly-negative floats)
__device__ __forceinline__ unsigned fkey(float f) {
    int i = __float_as_int(f);
    return (i >= 0) ? ((unsigned)i | 0x80000000u) : (unsigned)(~i);
}
__device__ __forceinline__ float funkey(unsigned u) {
    int i = (u & 0x80000000u) ? (int)(u ^ 0x80000000u) : (int)(~u);
    return __int_as_float(i);
}

// ---------------- 0) dtype detection ----------------
__global__ void k_detect(const int* __restrict__ ei32, int E) {
    __shared__ int any;
    if (threadIdx.x == 0) any = 0;
    __syncthreads();
    int total = 2 * E;
    int stride = (total / 2) / 4096;
    if (stride < 1) stride = 1;
    for (int q = threadIdx.x; q < 4096; q += blockDim.x) {
        long long w = 1 + 2 * (long long)q * stride;
        if (w < total && ei32[w] != 0) { any = 1; break; }
    }
    __syncthreads();
    if (threadIdx.x == 0) g_is64 = (any == 0) ? 1 : 0;
}

// ---------------- 1) GEMM xp = x@W, fused attention logits + seeding ----------------
__global__ void k_gemm(const float* __restrict__ x, const float* __restrict__ W,
                       const float* __restrict__ att_src, const float* __restrict__ att_dst,
                       int N) {
    __shared__ float xs[64 * 128];  // 32 KB
    __shared__ float ws[32 * 128];  // 16 KB
    const int tid = threadIdx.x;       // 256 threads
    const int tx = tid & 15;           // 16 col-groups x 8 cols
    const int ty = tid >> 4;           // 16 row-groups x 4 rows
    const int row0 = blockIdx.x * 64;

    {   // load x tile
        float4* xs4 = (float4*)xs;
        const float4* x4 = (const float4*)x;
        #pragma unroll
        for (int q = 0; q < 8; ++q) {
            int fi = q * 256 + tid;
            int r = fi >> 5, c4 = fi & 31;
            int gr = row0 + r;
            float4 v = make_float4(0.f, 0.f, 0.f, 0.f);
            if (gr < N) v = x4[gr * 32 + c4];
            xs4[fi] = v;
        }
    }

    float acc[4][8];
    #pragma unroll
    for (int i = 0; i < 4; ++i)
        #pragma unroll
        for (int j = 0; j < 8; ++j) acc[i][j] = 0.f;

    for (int kt = 0; kt < 4; ++kt) {
        __syncthreads();
        {   // load W k-tile
            float4* ws4 = (float4*)ws;
            const float4* W4 = (const float4*)W;
            #pragma unroll
            for (int q = 0; q < 4; ++q) {
                int fi = q * 256 + tid;
                int r = fi >> 5, c4 = fi & 31;
                ws4[fi] = W4[(kt * 32 + r) * 32 + c4];
            }
        }
        __syncthreads();
        #pragma unroll
        for (int k = 0; k < 32; ++k) {
            float xv[4];
            #pragma unroll
            for (int i = 0; i < 4; ++i) xv[i] = xs[(ty * 4 + i) * 128 + kt * 32 + k];
            float4 wa = ((float4*)ws)[k * 32 + tx * 2];
            float4 wb = ((float4*)ws)[k * 32 + tx * 2 + 1];
            #pragma unroll
            for (int i = 0; i < 4; ++i) {
                acc[i][0] += xv[i] * wa.x; acc[i][1] += xv[i] * wa.y;
                acc[i][2] += xv[i] * wa.z; acc[i][3] += xv[i] * wa.w;
                acc[i][4] += xv[i] * wb.x; acc[i][5] += xv[i] * wb.y;
                acc[i][6] += xv[i] * wb.z; acc[i][7] += xv[i] * wb.w;
            }
        }
    }

    // write xp
    #pragma unroll
    for (int i = 0; i < 4; ++i) {
        int gr = row0 + ty * 4 + i;
        if (gr < N) {
            float4* o = (float4*)&g_xp[gr * 128 + tx * 8];
            o[0] = make_float4(acc[i][0], acc[i][1], acc[i][2], acc[i][3]);
            o[1] = make_float4(acc[i][4], acc[i][5], acc[i][6], acc[i][7]);
        }
    }

    // fused attention logits: per-row dot with att vectors, reduce across 16 tx lanes
    float4 as0 = ((const float4*)att_src)[tx * 2];
    float4 as1 = ((const float4*)att_src)[tx * 2 + 1];
    float4 ad0 = ((const float4*)att_dst)[tx * 2];
    float4 ad1 = ((const float4*)att_dst)[tx * 2 + 1];
    float ds[4], dd[4];
    #pragma unroll
    for (int i = 0; i < 4; ++i) {
        ds[i] = acc[i][0]*as0.x + acc[i][1]*as0.y + acc[i][2]*as0.z + acc[i][3]*as0.w
              + acc[i][4]*as1.x + acc[i][5]*as1.y + acc[i][6]*as1.z + acc[i][7]*as1.w;
        dd[i] = acc[i][0]*ad0.x + acc[i][1]*ad0.y + acc[i][2]*ad0.z + acc[i][3]*ad0.w
              + acc[i][4]*ad1.x + acc[i][5]*ad1.y + acc[i][6]*ad1.z + acc[i][7]*ad1.w;
    }
    #pragma unroll
    for (int off = 1; off < 16; off <<= 1) {
        #pragma unroll
        for (int i = 0; i < 4; ++i) {
            ds[i] += __shfl_xor_sync(0xffffffffu, ds[i], off);
            dd[i] += __shfl_xor_sync(0xffffffffu, dd[i], off);
        }
    }
    if (tx == 0) {
        #pragma unroll
        for (int i = 0; i < 4; ++i) {
            int gr = row0 + ty * 4 + i;
            if (gr < N) {
                g_asrc[gr] = ds[i];
                g_adst[gr] = dd[i];
                g_hist[gr] = 1;        // self loop
                g_maxkey[gr] = 0u;     // below any finite float key
            }
        }
    }
}

// ---------------- 2) histogram of dst (4 edges/thread for MLP) ----------------
__global__ void k_hist(const void* __restrict__ ei, int E) {
    int base = (blockIdx.x * blockDim.x + threadIdx.x) * 4;
    int is64 = g_is64;
    #pragma unroll
    for (int q = 0; q < 4; ++q) {
        int e = base + q;
        if (e < E) atomicAdd(&g_hist[edge_at(ei, E + e, is64)], 1);
    }
}

// ---------------- 3) single-block exclusive scan -> rowstart & cursor ----------------
__global__ void k_scan(int N) {
    __shared__ int sp[1024];
    int tid = threadIdx.x;
    int C = (N + 1023) >> 10;
    int b = tid * C;
    int e = min(b + C, N);
    int sum = 0;
    for (int i = b; i < e; ++i) sum += g_hist[i];
    sp[tid] = sum;
    __syncthreads();
    for (int off = 1; off < 1024; off <<= 1) {
        int v = (tid >= off) ? sp[tid - off] : 0;
        __syncthreads();
        sp[tid] += v;
        __syncthreads();
    }
    int run = (tid == 0) ? 0 : sp[tid - 1];
    for (int i = b; i < e; ++i) {
        int h = g_hist[i];
        g_rowstart[i] = run;
        g_cursor[i]   = run;
        run += h;
    }
    if (tid == 1023) g_rowstart[N] = sp[1023];
}

// ---------------- 4) scatter: sort edges by dst + compute logits + segment max ----------------
__global__ void k_scatter(const void* __restrict__ ei, int N, int E) {
    int idx = blockIdx.x * blockDim.x + threadIdx.x;
    int is64 = g_is64;
    if (idx < E) {
        int d = edge_at(ei, E + idx, is64);
        int s = edge_at(ei, idx, is64);
        float e = g_asrc[s] + g_adst[d];
        e = (e >= 0.f) ? e : 0.2f * e;
        int pos = atomicAdd(&g_cursor[d], 1);
        g_edge[pos] = make_int2(s, __float_as_int(e));
        atomicMax(&g_maxkey[d], fkey(e));
    } else if (idx < E + N) {
        int i = idx - E;
        float e = g_asrc[i] + g_adst[i];
        e = (e >= 0.f) ? e : 0.2f * e;
        int pos = atomicAdd(&g_cursor[i], 1);
        g_edge[pos] = make_int2(i, __float_as_int(e));   // self loop
        atomicMax(&g_maxkey[i], fkey(e));
    }
}

// ---------------- 5) warp-per-node: weights w = exp(e-m), inv = 1/sum ----------------
__global__ void k_stats(int N) {
    int warp = (blockIdx.x * blockDim.x + threadIdx.x) >> 5;
    int lane = threadIdx.x & 31;
    if (warp >= N) return;
    int beg = g_rowstart[warp];
    int end = g_rowstart[warp + 1];
    float m = funkey(g_maxkey[warp]);
    float sum = 0.f;
    for (int j = beg + lane; j < end; j += 32) {
        float w = __expf(__int_as_float(g_edge[j].y) - m);
        g_wsorted[j] = w;
        sum += w;
    }
    #pragma unroll
    for (int o = 16; o > 0; o >>= 1) sum += __shfl_xor_sync(0xffffffffu, sum, o);
    if (lane == 0) g_inv[warp] = 1.f / sum;
}

// ---------------- 6) pure weighted gather: one block(128) per dst node ----------------
__global__ void k_agg(const float* __restrict__ bias, float* __restrict__ out, int N) {
    const int d = blockIdx.x;
    const int tid = threadIdx.x;
    __shared__ float w_s[128];
    __shared__ int   s_s[128];

    const int beg = g_rowstart[d];
    const int end = g_rowstart[d + 1];

    float acc0 = 0.f, acc1 = 0.f, acc2 = 0.f, acc3 = 0.f;
    for (int base = beg; base < end; base += 128) {
        int j = base + tid;
        if (j < end) {
            s_s[tid] = g_edge[j].x;
            w_s[tid] = g_wsorted[j];
        }
        __syncthreads();
        int cnt = min(128, end - base);
        int jj = 0;
        for (; jj + 3 < cnt; jj += 4) {
            float v0 = g_xp[(size_t)s_s[jj]     * 128 + tid];
            float v1 = g_xp[(size_t)s_s[jj + 1] * 128 + tid];
            float v2 = g_xp[(size_t)s_s[jj + 2] * 128 + tid];
            float v3 = g_xp[(size_t)s_s[jj + 3] * 128 + tid];
            acc0 += w_s[jj]     * v0;
            acc1 += w_s[jj + 1] * v1;
            acc2 += w_s[jj + 2] * v2;
            acc3 += w_s[jj + 3] * v3;
        }
        for (; jj < cnt; ++jj) acc0 += w_s[jj] * g_xp[(size_t)s_s[jj] * 128 + tid];
        __syncthreads();
    }
    out[(size_t)d * 128 + tid] = (acc0 + acc1 + acc2 + acc3) * g_inv[d] + bias[tid];
}

// ---------------- launch ----------------
extern "C" void kernel_launch(void* const* d_in, const int* in_sizes, int n_in,
                              void* d_out, int out_size) {
    const float* x        = (const float*)d_in[0];
    const float* W        = (const float*)d_in[1];
    const float* att_src  = (const float*)d_in[2];
    const float* att_dst  = (const float*)d_in[3];
    const float* bias     = (const float*)d_in[4];
    const void*  ei       = d_in[5];   // [2, E] int32 or int64 (device-detected)

    const int N = in_sizes[0] / F;
    const int E = in_sizes[5] / 2;
    float* out = (float*)d_out;

    k_detect <<<1, 256>>>((const int*)ei, E);
    k_gemm   <<<(N + 63) / 64, 256>>>(x, W, att_src, att_dst, N);
    k_hist   <<<(E + 1023) / 1024, 256>>>(ei, E);
    k_scan   <<<1, 1024>>>(N);
    k_scatter<<<(E + N + 255) / 256, 256>>>(ei, N, E);
    k_stats  <<<(N + 7) / 8, 256>>>(N);
    k_agg    <<<N, 128>>>(bias, out, N);
}

// round 6
// speedup vs baseline: 1.7385x; 1.4140x over previous
#include <cuda_runtime.h>

#define F 128
#define NMAX 65536
#define EMAX 1200000
#define SCAN_TILE 1024
#define MAXBLK (NMAX / SCAN_TILE)   // 64

// ---------------- scratch (no allocations allowed) ----------------
__device__ float    g_xp[NMAX * F];        // x @ W
__device__ float    g_asrc[NMAX];          // xp @ att_src
__device__ float    g_adst[NMAX];          // xp @ att_dst
__device__ int      g_hist[NMAX];          // in-degree (incl. self loop)
__device__ int      g_rowstart[NMAX + 1];  // CSR offsets by dst
__device__ int      g_cursor[NMAX];        // scatter cursors
__device__ int      g_bsum[MAXBLK];        // per-scan-block totals
__device__ int      g_boff[MAXBLK];        // exclusive block offsets
__device__ int2     g_edge[EMAX];          // (src, logit-bits) grouped by dst
__device__ float    g_wsorted[EMAX];       // exp(e - m), dst-grouped
__device__ unsigned g_maxkey[NMAX];        // ordered-uint encoding of segment max
__device__ float    g_inv[NMAX];           // 1 / sum(exp)
__device__ int      g_is64;                // 1 if edge_index is int64

__device__ __forceinline__ int edge_at(const void* ei, int idx, int is64) {
    if (is64) return (int)((const long long*)ei)[idx];
    return ((const int*)ei)[idx];
}

// monotone float -> uint key (for atomicMax on possibly-negative floats)
__device__ __forceinline__ unsigned fkey(float f) {
    int i = __float_as_int(f);
    return (i >= 0) ? ((unsigned)i | 0x80000000u) : (unsigned)(~i);
}
__device__ __forceinline__ float funkey(unsigned u) {
    int i = (u & 0x80000000u) ? (int)(u ^ 0x80000000u) : (int)(~u);
    return __int_as_float(i);
}

// ---------------- 0) dtype detection ----------------
__global__ void k_detect(const int* __restrict__ ei32, int E) {
    __shared__ int any;
    if (threadIdx.x == 0) any = 0;
    __syncthreads();
    int total = 2 * E;
    int stride = (total / 2) / 4096;
    if (stride < 1) stride = 1;
    for (int q = threadIdx.x; q < 4096; q += blockDim.x) {
        long long w = 1 + 2 * (long long)q * stride;
        if (w < total && ei32[w] != 0) { any = 1; break; }
    }
    __syncthreads();
    if (threadIdx.x == 0) g_is64 = (any == 0) ? 1 : 0;
}

// ---------------- 1) GEMM xp = x@W, fused attention logits + seeding ----------------
__global__ void k_gemm(const float* __restrict__ x, const float* __restrict__ W,
                       const float* __restrict__ att_src, const float* __restrict__ att_dst,
                       int N) {
    __shared__ float xs[64 * 128];  // 32 KB
    __shared__ float ws[32 * 128];  // 16 KB
    const int tid = threadIdx.x;       // 256 threads
    const int tx = tid & 15;
    const int ty = tid >> 4;
    const int row0 = blockIdx.x * 64;

    {   // load x tile
        float4* xs4 = (float4*)xs;
        const float4* x4 = (const float4*)x;
        #pragma unroll
        for (int q = 0; q < 8; ++q) {
            int fi = q * 256 + tid;
            int r = fi >> 5, c4 = fi & 31;
            int gr = row0 + r;
            float4 v = make_float4(0.f, 0.f, 0.f, 0.f);
            if (gr < N) v = x4[gr * 32 + c4];
            xs4[fi] = v;
        }
    }

    float acc[4][8];
    #pragma unroll
    for (int i = 0; i < 4; ++i)
        #pragma unroll
        for (int j = 0; j < 8; ++j) acc[i][j] = 0.f;

    for (int kt = 0; kt < 4; ++kt) {
        __syncthreads();
        {   // load W k-tile
            float4* ws4 = (float4*)ws;
            const float4* W4 = (const float4*)W;
            #pragma unroll
            for (int q = 0; q < 4; ++q) {
                int fi = q * 256 + tid;
                int r = fi >> 5, c4 = fi & 31;
                ws4[fi] = W4[(kt * 32 + r) * 32 + c4];
            }
        }
        __syncthreads();
        #pragma unroll
        for (int k = 0; k < 32; ++k) {
            float xv[4];
            #pragma unroll
            for (int i = 0; i < 4; ++i) xv[i] = xs[(ty * 4 + i) * 128 + kt * 32 + k];
            float4 wa = ((float4*)ws)[k * 32 + tx * 2];
            float4 wb = ((float4*)ws)[k * 32 + tx * 2 + 1];
            #pragma unroll
            for (int i = 0; i < 4; ++i) {
                acc[i][0] += xv[i] * wa.x; acc[i][1] += xv[i] * wa.y;
                acc[i][2] += xv[i] * wa.z; acc[i][3] += xv[i] * wa.w;
                acc[i][4] += xv[i] * wb.x; acc[i][5] += xv[i] * wb.y;
                acc[i][6] += xv[i] * wb.z; acc[i][7] += xv[i] * wb.w;
            }
        }
    }

    // write xp
    #pragma unroll
    for (int i = 0; i < 4; ++i) {
        int gr = row0 + ty * 4 + i;
        if (gr < N) {
            float4* o = (float4*)&g_xp[gr * 128 + tx * 8];
            o[0] = make_float4(acc[i][0], acc[i][1], acc[i][2], acc[i][3]);
            o[1] = make_float4(acc[i][4], acc[i][5], acc[i][6], acc[i][7]);
        }
    }

    // fused attention logits
    float4 as0 = ((const float4*)att_src)[tx * 2];
    float4 as1 = ((const float4*)att_src)[tx * 2 + 1];
    float4 ad0 = ((const float4*)att_dst)[tx * 2];
    float4 ad1 = ((const float4*)att_dst)[tx * 2 + 1];
    float ds[4], dd[4];
    #pragma unroll
    for (int i = 0; i < 4; ++i) {
        ds[i] = acc[i][0]*as0.x + acc[i][1]*as0.y + acc[i][2]*as0.z + acc[i][3]*as0.w
              + acc[i][4]*as1.x + acc[i][5]*as1.y + acc[i][6]*as1.z + acc[i][7]*as1.w;
        dd[i] = acc[i][0]*ad0.x + acc[i][1]*ad0.y + acc[i][2]*ad0.z + acc[i][3]*ad0.w
              + acc[i][4]*ad1.x + acc[i][5]*ad1.y + acc[i][6]*ad1.z + acc[i][7]*ad1.w;
    }
    #pragma unroll
    for (int off = 1; off < 16; off <<= 1) {
        #pragma unroll
        for (int i = 0; i < 4; ++i) {
            ds[i] += __shfl_xor_sync(0xffffffffu, ds[i], off);
            dd[i] += __shfl_xor_sync(0xffffffffu, dd[i], off);
        }
    }
    if (tx == 0) {
        #pragma unroll
        for (int i = 0; i < 4; ++i) {
            int gr = row0 + ty * 4 + i;
            if (gr < N) {
                g_asrc[gr] = ds[i];
                g_adst[gr] = dd[i];
                g_hist[gr] = 1;        // self loop
                g_maxkey[gr] = 0u;
            }
        }
    }
}

// ---------------- 2) histogram of dst (4 edges/thread for MLP) ----------------
__global__ void k_hist(const void* __restrict__ ei, int E) {
    int base = (blockIdx.x * blockDim.x + threadIdx.x) * 4;
    int is64 = g_is64;
    #pragma unroll
    for (int q = 0; q < 4; ++q) {
        int e = base + q;
        if (e < E) atomicAdd(&g_hist[edge_at(ei, E + e, is64)], 1);
    }
}

// ---------------- 3a) per-tile exclusive scan (256 thr x 4 elems = 1024/block) ----------------
__global__ void k_scanA(int N) {
    __shared__ int wsum[8];
    __shared__ int blktot;
    const int tid = threadIdx.x;
    const int lane = tid & 31, wid = tid >> 5;
    const int i0 = blockIdx.x * SCAN_TILE + tid * 4;

    int v0 = 0, v1 = 0, v2 = 0, v3 = 0;
    if (i0 + 3 < N) {
        int4 v = *(const int4*)&g_hist[i0];
        v0 = v.x; v1 = v.y; v2 = v.z; v3 = v.w;
    } else {
        if (i0 < N)     v0 = g_hist[i0];
        if (i0 + 1 < N) v1 = g_hist[i0 + 1];
        if (i0 + 2 < N) v2 = g_hist[i0 + 2];
        if (i0 + 3 < N) v3 = g_hist[i0 + 3];
    }
    int s0 = v0, s1 = s0 + v1, s2 = s1 + v2, s3 = s2 + v3;   // thread-inclusive
    int t = s3;
    int incl = t;
    #pragma unroll
    for (int off = 1; off < 32; off <<= 1) {
        int n = __shfl_up_sync(0xffffffffu, incl, off);
        if (lane >= off) incl += n;
    }
    if (lane == 31) wsum[wid] = incl;
    __syncthreads();
    if (wid == 0 && lane < 8) {
        int w = wsum[lane];
        int wi = w;
        #pragma unroll
        for (int off = 1; off < 8; off <<= 1) {
            int n = __shfl_up_sync(0xffu, wi, off);
            if (lane >= off) wi += n;
        }
        wsum[lane] = wi - w;           // exclusive warp offset
        if (lane == 7) blktot = wi;    // block total
    }
    __syncthreads();
    int base = wsum[wid] + (incl - t);  // thread-exclusive base in block
    if (i0 < N)     g_rowstart[i0]     = base;
    if (i0 + 1 < N) g_rowstart[i0 + 1] = base + s0;
    if (i0 + 2 < N) g_rowstart[i0 + 2] = base + s1;
    if (i0 + 3 < N) g_rowstart[i0 + 3] = base + s2;
    if (tid == 0) g_bsum[blockIdx.x] = blktot;
}

// ---------------- 3b) scan of block totals (<=64 entries) ----------------
__global__ void k_scanB(int nblk) {
    __shared__ int sp[MAXBLK];
    int tid = threadIdx.x;   // 64 threads
    int v = (tid < nblk) ? g_bsum[tid] : 0;
    sp[tid] = v;
    __syncthreads();
    for (int off = 1; off < MAXBLK; off <<= 1) {
        int n = (tid >= off) ? sp[tid - off] : 0;
        __syncthreads();
        sp[tid] += n;
        __syncthreads();
    }
    if (tid < nblk) g_boff[tid] = sp[tid] - v;   // exclusive
}

// ---------------- 3c) apply block offsets -> final rowstart & cursor ----------------
__global__ void k_scanC(int N, int totalEN) {
    int i = blockIdx.x * blockDim.x + threadIdx.x;
    if (i < N) {
        int r = g_rowstart[i] + g_boff[i >> 10];
        g_rowstart[i] = r;
        g_cursor[i]   = r;
    }
    if (i == 0) g_rowstart[N] = totalEN;
}

// ---------------- 4) scatter: sort edges by dst + logits + segment max ----------------
__global__ void k_scatter(const void* __restrict__ ei, int N, int E) {
    int idx = blockIdx.x * blockDim.x + threadIdx.x;
    int is64 = g_is64;
    if (idx < E) {
        int d = edge_at(ei, E + idx, is64);
        int s = edge_at(ei, idx, is64);
        float e = g_asrc[s] + g_adst[d];
        e = (e >= 0.f) ? e : 0.2f * e;
        int pos = atomicAdd(&g_cursor[d], 1);
        g_edge[pos] = make_int2(s, __float_as_int(e));
        atomicMax(&g_maxkey[d], fkey(e));
    } else if (idx < E + N) {
        int i = idx - E;
        float e = g_asrc[i] + g_adst[i];
        e = (e >= 0.f) ? e : 0.2f * e;
        int pos = atomicAdd(&g_cursor[i], 1);
        g_edge[pos] = make_int2(i, __float_as_int(e));   // self loop
        atomicMax(&g_maxkey[i], fkey(e));
    }
}

// ---------------- 5) warp-per-node: w = exp(e-m), inv = 1/sum ----------------
__global__ void k_stats(int N) {
    int warp = (blockIdx.x * blockDim.x + threadIdx.x) >> 5;
    int lane = threadIdx.x & 31;
    if (warp >= N) return;
    int beg = g_rowstart[warp];
    int end = g_rowstart[warp + 1];
    float m = funkey(g_maxkey[warp]);
    float sum = 0.f;
    for (int j = beg + lane; j < end; j += 32) {
        float w = __expf(__int_as_float(g_edge[j].y) - m);
        g_wsorted[j] = w;
        sum += w;
    }
    #pragma unroll
    for (int o = 16; o > 0; o >>= 1) sum += __shfl_xor_sync(0xffffffffu, sum, o);
    if (lane == 0) g_inv[warp] = 1.f / sum;
}

// ---------------- 6) pure weighted gather: one block(128) per dst node ----------------
__global__ void k_agg(const float* __restrict__ bias, float* __restrict__ out, int N) {
    const int d = blockIdx.x;
    const int tid = threadIdx.x;
    __shared__ float w_s[128];
    __shared__ int   s_s[128];

    const int beg = g_rowstart[d];
    const int end = g_rowstart[d + 1];

    float acc0 = 0.f, acc1 = 0.f, acc2 = 0.f, acc3 = 0.f;
    for (int base = beg; base < end; base += 128) {
        int j = base + tid;
        if (j < end) {
            s_s[tid] = g_edge[j].x;
            w_s[tid] = g_wsorted[j];
        }
        __syncthreads();
        int cnt = min(128, end - base);
        int jj = 0;
        for (; jj + 3 < cnt; jj += 4) {
            float v0 = g_xp[(size_t)s_s[jj]     * 128 + tid];
            float v1 = g_xp[(size_t)s_s[jj + 1] * 128 + tid];
            float v2 = g_xp[(size_t)s_s[jj + 2] * 128 + tid];
            float v3 = g_xp[(size_t)s_s[jj + 3] * 128 + tid];
            acc0 += w_s[jj]     * v0;
            acc1 += w_s[jj + 1] * v1;
            acc2 += w_s[jj + 2] * v2;
            acc3 += w_s[jj + 3] * v3;
        }
        for (; jj < cnt; ++jj) acc0 += w_s[jj] * g_xp[(size_t)s_s[jj] * 128 + tid];
        __syncthreads();
    }
    out[(size_t)d * 128 + tid] = (acc0 + acc1 + acc2 + acc3) * g_inv[d] + bias[tid];
}

// ---------------- launch ----------------
extern "C" void kernel_launch(void* const* d_in, const int* in_sizes, int n_in,
                              void* d_out, int out_size) {
    const float* x        = (const float*)d_in[0];
    const float* W        = (const float*)d_in[1];
    const float* att_src  = (const float*)d_in[2];
    const float* att_dst  = (const float*)d_in[3];
    const float* bias     = (const float*)d_in[4];
    const void*  ei       = d_in[5];

    const int N = in_sizes[0] / F;
    const int E = in_sizes[5] / 2;
    const int nblk = (N + SCAN_TILE - 1) / SCAN_TILE;
    float* out = (float*)d_out;

    k_detect <<<1, 256>>>((const int*)ei, E);
    k_gemm   <<<(N + 63) / 64, 256>>>(x, W, att_src, att_dst, N);
    k_hist   <<<(E + 1023) / 1024, 256>>>(ei, E);
    k_scanA  <<<nblk, 256>>>(N);
    k_scanB  <<<1, MAXBLK>>>(nblk);
    k_scanC  <<<(N + 255) / 256, 256>>>(N, E + N);
    k_scatter<<<(E + N + 255) / 256, 256>>>(ei, N, E);
    k_stats  <<<(N + 7) / 8, 256>>>(N);
    k_agg    <<<N, 128>>>(bias, out, N);
}

// round 7
// speedup vs baseline: 2.0240x; 1.1642x over previous
#include <cuda_runtime.h>

#define F 128
#define NMAX 65536
#define EMAX 1200000
#define SCAN_TILE 1024
#define MAXBLK (NMAX / SCAN_TILE)   // 64

// ---------------- scratch (no allocations allowed) ----------------
__device__ float    g_xp[NMAX * F];        // x @ W
__device__ float    g_asrc[NMAX];          // xp @ att_src
__device__ float    g_adst[NMAX];          // xp @ att_dst
__device__ int      g_hist[NMAX];          // in-degree (incl. self loop)
__device__ int      g_rowstart[NMAX + 1];  // CSR offsets by dst
__device__ int      g_cursor[NMAX];        // scatter cursors
__device__ int      g_bsum[MAXBLK];        // per-scan-block totals
__device__ int      g_boff[MAXBLK];        // exclusive block offsets
__device__ int2     g_edge[EMAX];          // (src, logit-bits) grouped by dst
__device__ unsigned g_maxkey[NMAX];        // ordered-uint encoding of segment max
__device__ int      g_is64;                // 1 if edge_index is int64

__device__ __forceinline__ int edge_at(const void* ei, int idx, int is64) {
    if (is64) return (int)((const long long*)ei)[idx];
    return ((const int*)ei)[idx];
}

// monotone float -> uint key (for atomicMax on possibly-negative floats)
__device__ __forceinline__ unsigned fkey(float f) {
    int i = __float_as_int(f);
    return (i >= 0) ? ((unsigned)i | 0x80000000u) : (unsigned)(~i);
}
__device__ __forceinline__ float funkey(unsigned u) {
    int i = (u & 0x80000000u) ? (int)(u ^ 0x80000000u) : (int)(~u);
    return __int_as_float(i);
}

// ---------------- 0) dtype detection ----------------
__global__ void k_detect(const int* __restrict__ ei32, int E) {
    __shared__ int any;
    if (threadIdx.x == 0) any = 0;
    __syncthreads();
    int total = 2 * E;
    int stride = (total / 2) / 4096;
    if (stride < 1) stride = 1;
    for (int q = threadIdx.x; q < 4096; q += blockDim.x) {
        long long w = 1 + 2 * (long long)q * stride;
        if (w < total && ei32[w] != 0) { any = 1; break; }
    }
    __syncthreads();
    if (threadIdx.x == 0) g_is64 = (any == 0) ? 1 : 0;
}

// ---------------- 1) GEMM xp = x@W, fused attention logits + seeding ----------------
__global__ void k_gemm(const float* __restrict__ x, const float* __restrict__ W,
                       const float* __restrict__ att_src, const float* __restrict__ att_dst,
                       int N) {
    __shared__ float xs[64 * 128];  // 32 KB
    __shared__ float ws[32 * 128];  // 16 KB
    const int tid = threadIdx.x;       // 256 threads
    const int tx = tid & 15;
    const int ty = tid >> 4;
    const int row0 = blockIdx.x * 64;

    {   // load x tile
        float4* xs4 = (float4*)xs;
        const float4* x4 = (const float4*)x;
        #pragma unroll
        for (int q = 0; q < 8; ++q) {
            int fi = q * 256 + tid;
            int r = fi >> 5, c4 = fi & 31;
            int gr = row0 + r;
            float4 v = make_float4(0.f, 0.f, 0.f, 0.f);
            if (gr < N) v = x4[gr * 32 + c4];
            xs4[fi] = v;
        }
    }

    float acc[4][8];
    #pragma unroll
    for (int i = 0; i < 4; ++i)
        #pragma unroll
        for (int j = 0; j < 8; ++j) acc[i][j] = 0.f;

    for (int kt = 0; kt < 4; ++kt) {
        __syncthreads();
        {   // load W k-tile
            float4* ws4 = (float4*)ws;
            const float4* W4 = (const float4*)W;
            #pragma unroll
            for (int q = 0; q < 4; ++q) {
                int fi = q * 256 + tid;
                int r = fi >> 5, c4 = fi & 31;
                ws4[fi] = W4[(kt * 32 + r) * 32 + c4];
            }
        }
        __syncthreads();
        #pragma unroll
        for (int k = 0; k < 32; ++k) {
            float xv[4];
            #pragma unroll
            for (int i = 0; i < 4; ++i) xv[i] = xs[(ty * 4 + i) * 128 + kt * 32 + k];
            float4 wa = ((float4*)ws)[k * 32 + tx * 2];
            float4 wb = ((float4*)ws)[k * 32 + tx * 2 + 1];
            #pragma unroll
            for (int i = 0; i < 4; ++i) {
                acc[i][0] += xv[i] * wa.x; acc[i][1] += xv[i] * wa.y;
                acc[i][2] += xv[i] * wa.z; acc[i][3] += xv[i] * wa.w;
                acc[i][4] += xv[i] * wb.x; acc[i][5] += xv[i] * wb.y;
                acc[i][6] += xv[i] * wb.z; acc[i][7] += xv[i] * wb.w;
            }
        }
    }

    // write xp
    #pragma unroll
    for (int i = 0; i < 4; ++i) {
        int gr = row0 + ty * 4 + i;
        if (gr < N) {
            float4* o = (float4*)&g_xp[gr * 128 + tx * 8];
            o[0] = make_float4(acc[i][0], acc[i][1], acc[i][2], acc[i][3]);
            o[1] = make_float4(acc[i][4], acc[i][5], acc[i][6], acc[i][7]);
        }
    }

    // fused attention logits
    float4 as0 = ((const float4*)att_src)[tx * 2];
    float4 as1 = ((const float4*)att_src)[tx * 2 + 1];
    float4 ad0 = ((const float4*)att_dst)[tx * 2];
    float4 ad1 = ((const float4*)att_dst)[tx * 2 + 1];
    float ds[4], dd[4];
    #pragma unroll
    for (int i = 0; i < 4; ++i) {
        ds[i] = acc[i][0]*as0.x + acc[i][1]*as0.y + acc[i][2]*as0.z + acc[i][3]*as0.w
              + acc[i][4]*as1.x + acc[i][5]*as1.y + acc[i][6]*as1.z + acc[i][7]*as1.w;
        dd[i] = acc[i][0]*ad0.x + acc[i][1]*ad0.y + acc[i][2]*ad0.z + acc[i][3]*ad0.w
              + acc[i][4]*ad1.x + acc[i][5]*ad1.y + acc[i][6]*ad1.z + acc[i][7]*ad1.w;
    }
    #pragma unroll
    for (int off = 1; off < 16; off <<= 1) {
        #pragma unroll
        for (int i = 0; i < 4; ++i) {
            ds[i] += __shfl_xor_sync(0xffffffffu, ds[i], off);
            dd[i] += __shfl_xor_sync(0xffffffffu, dd[i], off);
        }
    }
    if (tx == 0) {
        #pragma unroll
        for (int i = 0; i < 4; ++i) {
            int gr = row0 + ty * 4 + i;
            if (gr < N) {
                g_asrc[gr] = ds[i];
                g_adst[gr] = dd[i];
                g_hist[gr] = 1;        // self loop
                g_maxkey[gr] = 0u;
            }
        }
    }
}

// ---------------- 2) histogram of dst (4 edges/thread for MLP) ----------------
__global__ void k_hist(const void* __restrict__ ei, int E) {
    int base = (blockIdx.x * blockDim.x + threadIdx.x) * 4;
    int is64 = g_is64;
    #pragma unroll
    for (int q = 0; q < 4; ++q) {
        int e = base + q;
        if (e < E) atomicAdd(&g_hist[edge_at(ei, E + e, is64)], 1);
    }
}

// ---------------- 3a) per-tile exclusive scan (256 thr x 4 elems = 1024/block) ----------------
__global__ void k_scanA(int N) {
    __shared__ int wsum[8];
    __shared__ int blktot;
    const int tid = threadIdx.x;
    const int lane = tid & 31, wid = tid >> 5;
    const int i0 = blockIdx.x * SCAN_TILE + tid * 4;

    int v0 = 0, v1 = 0, v2 = 0, v3 = 0;
    if (i0 + 3 < N) {
        int4 v = *(const int4*)&g_hist[i0];
        v0 = v.x; v1 = v.y; v2 = v.z; v3 = v.w;
    } else {
        if (i0 < N)     v0 = g_hist[i0];
        if (i0 + 1 < N) v1 = g_hist[i0 + 1];
        if (i0 + 2 < N) v2 = g_hist[i0 + 2];
        if (i0 + 3 < N) v3 = g_hist[i0 + 3];
    }
    int s0 = v0, s1 = s0 + v1, s2 = s1 + v2, s3 = s2 + v3;   // thread-inclusive
    int t = s3;
    int incl = t;
    #pragma unroll
    for (int off = 1; off < 32; off <<= 1) {
        int n = __shfl_up_sync(0xffffffffu, incl, off);
        if (lane >= off) incl += n;
    }
    if (lane == 31) wsum[wid] = incl;
    __syncthreads();
    if (wid == 0 && lane < 8) {
        int w = wsum[lane];
        int wi = w;
        #pragma unroll
        for (int off = 1; off < 8; off <<= 1) {
            int n = __shfl_up_sync(0xffu, wi, off);
            if (lane >= off) wi += n;
        }
        wsum[lane] = wi - w;           // exclusive warp offset
        if (lane == 7) blktot = wi;    // block total
    }
    __syncthreads();
    int base = wsum[wid] + (incl - t);  // thread-exclusive base in block
    if (i0 < N)     g_rowstart[i0]     = base;
    if (i0 + 1 < N) g_rowstart[i0 + 1] = base + s0;
    if (i0 + 2 < N) g_rowstart[i0 + 2] = base + s1;
    if (i0 + 3 < N) g_rowstart[i0 + 3] = base + s2;
    if (tid == 0) g_bsum[blockIdx.x] = blktot;
}

// ---------------- 3b) scan of block totals (<=64 entries) ----------------
__global__ void k_scanB(int nblk) {
    __shared__ int sp[MAXBLK];
    int tid = threadIdx.x;   // 64 threads
    int v = (tid < nblk) ? g_bsum[tid] : 0;
    sp[tid] = v;
    __syncthreads();
    for (int off = 1; off < MAXBLK; off <<= 1) {
        int n = (tid >= off) ? sp[tid - off] : 0;
        __syncthreads();
        sp[tid] += n;
        __syncthreads();
    }
    if (tid < nblk) g_boff[tid] = sp[tid] - v;   // exclusive
}

// ---------------- 3c) apply block offsets -> final rowstart & cursor ----------------
__global__ void k_scanC(int N, int totalEN) {
    int i = blockIdx.x * blockDim.x + threadIdx.x;
    if (i < N) {
        int r = g_rowstart[i] + g_boff[i >> 10];
        g_rowstart[i] = r;
        g_cursor[i]   = r;
    }
    if (i == 0) g_rowstart[N] = totalEN;
}

// ---------------- 4) scatter: sort edges by dst + logits + segment max ----------------
__global__ void k_scatter(const void* __restrict__ ei, int N, int E) {
    int idx = blockIdx.x * blockDim.x + threadIdx.x;
    int is64 = g_is64;
    if (idx < E) {
        int d = edge_at(ei, E + idx, is64);
        int s = edge_at(ei, idx, is64);
        float e = g_asrc[s] + g_adst[d];
        e = (e >= 0.f) ? e : 0.2f * e;
        int pos = atomicAdd(&g_cursor[d], 1);
        g_edge[pos] = make_int2(s, __float_as_int(e));
        atomicMax(&g_maxkey[d], fkey(e));
    } else if (idx < E + N) {
        int i = idx - E;
        float e = g_asrc[i] + g_adst[i];
        e = (e >= 0.f) ? e : 0.2f * e;
        int pos = atomicAdd(&g_cursor[i], 1);
        g_edge[pos] = make_int2(i, __float_as_int(e));   // self loop
        atomicMax(&g_maxkey[i], fkey(e));
    }
}

// ---------------- 5) fused softmax + gather: one WARP per dst node ----------------
// lane l owns feature channels [4l, 4l+4); per edge: 2 shuffles + 1 LDG.128
__global__ void k_agg(const float* __restrict__ bias, float* __restrict__ out, int N) {
    const int gw = (blockIdx.x * blockDim.x + threadIdx.x) >> 5;
    const int lane = threadIdx.x & 31;
    if (gw >= N) return;

    const int beg = g_rowstart[gw];
    const int end = g_rowstart[gw + 1];
    const float m = funkey(g_maxkey[gw]);

    float4 acc = make_float4(0.f, 0.f, 0.f, 0.f);
    float sum = 0.f;

    for (int c = beg; c < end; c += 32) {
        int j = c + lane;
        int src = 0;
        float w = 0.f;
        if (j < end) {
            int2 ed = g_edge[j];
            src = ed.x;
            w = __expf(__int_as_float(ed.y) - m);
        }
        float ws = w;
        #pragma unroll
        for (int o = 16; o > 0; o >>= 1) ws += __shfl_xor_sync(0xffffffffu, ws, o);
        sum += ws;

        int cnt = min(32, end - c);
        for (int jj = 0; jj < cnt; ++jj) {
            float wj = __shfl_sync(0xffffffffu, w, jj);
            int   sj = __shfl_sync(0xffffffffu, src, jj);
            float4 v = ((const float4*)(g_xp + (size_t)sj * 128))[lane];
            acc.x += wj * v.x; acc.y += wj * v.y;
            acc.z += wj * v.z; acc.w += wj * v.w;
        }
    }

    const float inv = 1.f / sum;
    float4 b4 = ((const float4*)bias)[lane];
    float4 o4 = make_float4(acc.x * inv + b4.x, acc.y * inv + b4.y,
                            acc.z * inv + b4.z, acc.w * inv + b4.w);
    ((float4*)(out + (size_t)gw * 128))[lane] = o4;
}

// ---------------- launch ----------------
extern "C" void kernel_launch(void* const* d_in, const int* in_sizes, int n_in,
                              void* d_out, int out_size) {
    const float* x        = (const float*)d_in[0];
    const float* W        = (const float*)d_in[1];
    const float* att_src  = (const float*)d_in[2];
    const float* att_dst  = (const float*)d_in[3];
    const float* bias     = (const float*)d_in[4];
    const void*  ei       = d_in[5];

    const int N = in_sizes[0] / F;
    const int E = in_sizes[5] / 2;
    const int nblk = (N + SCAN_TILE - 1) / SCAN_TILE;
    float* out = (float*)d_out;

    k_detect <<<1, 256>>>((const int*)ei, E);
    k_gemm   <<<(N + 63) / 64, 256>>>(x, W, att_src, att_dst, N);
    k_hist   <<<(E + 1023) / 1024, 256>>>(ei, E);
    k_scanA  <<<nblk, 256>>>(N);
    k_scanB  <<<1, MAXBLK>>>(nblk);
    k_scanC  <<<(N + 255) / 256, 256>>>(N, E + N);
    k_scatter<<<(E + N + 255) / 256, 256>>>(ei, N, E);
    k_agg    <<<(N + 7) / 8, 256>>>(bias, out, N);
}

// round 8
// speedup vs baseline: 2.4187x; 1.1950x over previous
#include <cuda_runtime.h>
#include <cstdint>

#define F 128
#define NMAX 65536
#define EMAX 1200000
#define SCAN_TILE 1024
#define MAXBLK (NMAX / SCAN_TILE)   // 64
#define XS_STRIDE 132               // floats; %32==4 -> conflict-free A frags
#define WS_STRIDE 136               // floats; %32==8 -> conflict-free B frags

// ---------------- scratch (no allocations allowed) ----------------
__device__ float    g_xp[NMAX * F];        // x @ W
__device__ float    g_asrc[NMAX];          // xp @ att_src
__device__ float    g_adst[NMAX];          // xp @ att_dst
__device__ int      g_hist[NMAX];          // in-degree (incl. self loop)
__device__ int      g_rowstart[NMAX + 1];  // CSR offsets by dst
__device__ int      g_cursor[NMAX];        // scatter cursors
__device__ int      g_bsum[MAXBLK];        // per-scan-block totals
__device__ int      g_boff[MAXBLK];        // exclusive block offsets
__device__ int2     g_edge[EMAX];          // (src, logit-bits) grouped by dst
__device__ unsigned g_maxkey[NMAX];        // ordered-uint encoding of segment max
__device__ int      g_is64;                // 1 if edge_index is int64

__device__ __forceinline__ int edge_at(const void* ei, int idx, int is64) {
    if (is64) return (int)((const long long*)ei)[idx];
    return ((const int*)ei)[idx];
}

__device__ __forceinline__ unsigned fkey(float f) {
    int i = __float_as_int(f);
    return (i >= 0) ? ((unsigned)i | 0x80000000u) : (unsigned)(~i);
}
__device__ __forceinline__ float funkey(unsigned u) {
    int i = (u & 0x80000000u) ? (int)(u ^ 0x80000000u) : (int)(~u);
    return __int_as_float(i);
}

// ---- tf32 helpers ----
__device__ __forceinline__ uint32_t cvt_tf32(float a) {
    uint32_t r;
    asm("cvt.rna.tf32.f32 %0, %1;" : "=r"(r) : "f"(a));
    return r;
}
__device__ __forceinline__ void split_tf32(float a, uint32_t& hi, uint32_t& lo) {
    hi = cvt_tf32(a);
    lo = cvt_tf32(a - __uint_as_float(hi));
}
__device__ __forceinline__ void mma_tf32(float* d, const uint32_t* a, const uint32_t* b) {
    asm volatile(
        "mma.sync.aligned.m16n8k8.row.col.f32.tf32.tf32.f32 "
        "{%0,%1,%2,%3}, {%4,%5,%6,%7}, {%8,%9}, {%0,%1,%2,%3};\n"
        : "+f"(d[0]), "+f"(d[1]), "+f"(d[2]), "+f"(d[3])
        : "r"(a[0]), "r"(a[1]), "r"(a[2]), "r"(a[3]), "r"(b[0]), "r"(b[1]));
}

// ---------------- 0) dtype detection ----------------
__global__ void k_detect(const int* __restrict__ ei32, int E) {
    __shared__ int any;
    if (threadIdx.x == 0) any = 0;
    __syncthreads();
    int total = 2 * E;
    int stride = (total / 2) / 4096;
    if (stride < 1) stride = 1;
    for (int q = threadIdx.x; q < 4096; q += blockDim.x) {
        long long w = 1 + 2 * (long long)q * stride;
        if (w < total && ei32[w] != 0) { any = 1; break; }
    }
    __syncthreads();
    if (threadIdx.x == 0) g_is64 = (any == 0) ? 1 : 0;
}

// ---------------- 1) TF32 tensor GEMM xp = x@W (+ fused attention logits) ----------------
// block tile: 64(M) x 128(N) x 128(K); 8 warps, warp tile 32x32
// split-precision: acc += aHi*bHi + aLo*bHi + aHi*bLo   (error ~2^-21)
__global__ void k_gemm(const float* __restrict__ x, const float* __restrict__ W,
                       const float* __restrict__ att_src, const float* __restrict__ att_dst,
                       int N) {
    __shared__ float xs[64 * XS_STRIDE];    // 33792 B, full-K x tile
    __shared__ float ws[16 * WS_STRIDE];    // 8704 B, W k-chunk
    __shared__ float att_sh[256];           // att_src | att_dst
    __shared__ float sdot[128];             // row dots: [0:64) src, [64:128) dst

    const int tid  = threadIdx.x;           // 256
    const int lane = tid & 31;
    const int w    = tid >> 5;
    const int g    = lane >> 2;             // 0..7
    const int t    = lane & 3;              // 0..3
    const int warp_m = (w & 1) * 32;
    const int warp_n = (w >> 1) * 32;
    const int row0 = blockIdx.x * 64;

    if (tid < 128) {
        att_sh[tid]       = att_src[tid];
        att_sh[128 + tid] = att_dst[tid];
        sdot[tid] = 0.f;
    }

    {   // load x tile (full K), zero-pad tail rows
        const float4* x4 = (const float4*)x;
        float4* xs4 = (float4*)xs;
        #pragma unroll
        for (int q = 0; q < 8; ++q) {
            int fi = q * 256 + tid;         // 0..2047
            int r = fi >> 5, c4 = fi & 31;
            int gr = row0 + r;
            float4 v = make_float4(0.f, 0.f, 0.f, 0.f);
            if (gr < N) v = x4[gr * 32 + c4];
            xs4[r * (XS_STRIDE / 4) + c4] = v;
        }
    }

    float acc[2][4][4];
    #pragma unroll
    for (int mi = 0; mi < 2; ++mi)
        #pragma unroll
        for (int ni = 0; ni < 4; ++ni)
            #pragma unroll
            for (int q = 0; q < 4; ++q) acc[mi][ni][q] = 0.f;

    for (int kt = 0; kt < 8; ++kt) {
        __syncthreads();
        {   // load W chunk rows [kt*16, kt*16+16)
            const float4* W4 = (const float4*)W;
            float4* ws4 = (float4*)ws;
            #pragma unroll
            for (int q = 0; q < 2; ++q) {
                int fi = q * 256 + tid;     // 0..511
                int r = fi >> 5, c4 = fi & 31;
                ws4[r * (WS_STRIDE / 4) + c4] = W4[(kt * 16 + r) * 32 + c4];
            }
        }
        __syncthreads();
        #pragma unroll
        for (int ks = 0; ks < 2; ++ks) {
            const int kk = ks * 8;
            // A fragments (a0:(g,t) a1:(g+8,t) a2:(g,t+4) a3:(g+8,t+4))
            uint32_t aHi[2][4], aLo[2][4];
            #pragma unroll
            for (int mi = 0; mi < 2; ++mi) {
                int r0 = warp_m + mi * 16 + g;
                int kc = kt * 16 + kk + t;
                split_tf32(xs[r0 * XS_STRIDE + kc],           aHi[mi][0], aLo[mi][0]);
                split_tf32(xs[(r0 + 8) * XS_STRIDE + kc],     aHi[mi][1], aLo[mi][1]);
                split_tf32(xs[r0 * XS_STRIDE + kc + 4],       aHi[mi][2], aLo[mi][2]);
                split_tf32(xs[(r0 + 8) * XS_STRIDE + kc + 4], aHi[mi][3], aLo[mi][3]);
            }
            // B fragments (b0:(t,g) b1:(t+4,g)) — B[k][n] col-major frag
            uint32_t bHi[4][2], bLo[4][2];
            #pragma unroll
            for (int ni = 0; ni < 4; ++ni) {
                int nc = warp_n + ni * 8 + g;
                split_tf32(ws[(kk + t) * WS_STRIDE + nc],     bHi[ni][0], bLo[ni][0]);
                split_tf32(ws[(kk + t + 4) * WS_STRIDE + nc], bHi[ni][1], bLo[ni][1]);
            }
            #pragma unroll
            for (int mi = 0; mi < 2; ++mi)
                #pragma unroll
                for (int ni = 0; ni < 4; ++ni) {
                    mma_tf32(acc[mi][ni], aHi[mi], bHi[ni]);
                    mma_tf32(acc[mi][ni], aLo[mi], bHi[ni]);
                    mma_tf32(acc[mi][ni], aHi[mi], bLo[ni]);
                }
        }
    }

    // ---- epilogue: write xp (c0:(g,2t) c1:(g,2t+1) c2:(g+8,2t) c3:(g+8,2t+1)) ----
    #pragma unroll
    for (int mi = 0; mi < 2; ++mi) {
        int gr = row0 + warp_m + mi * 16 + g;
        #pragma unroll
        for (int ni = 0; ni < 4; ++ni) {
            int col = warp_n + ni * 8 + 2 * t;
            if (gr < N)
                *(float2*)&g_xp[(size_t)gr * 128 + col] =
                    make_float2(acc[mi][ni][0], acc[mi][ni][1]);
            if (gr + 8 < N)
                *(float2*)&g_xp[(size_t)(gr + 8) * 128 + col] =
                    make_float2(acc[mi][ni][2], acc[mi][ni][3]);
        }
    }

    // ---- fused attention logits ----
    #pragma unroll
    for (int mi = 0; mi < 2; ++mi) {
        #pragma unroll
        for (int h = 0; h < 2; ++h) {       // h=0: row g, h=1: row g+8
            float ds = 0.f, dd = 0.f;
            #pragma unroll
            for (int ni = 0; ni < 4; ++ni) {
                int col = warp_n + ni * 8 + 2 * t;
                float c0 = acc[mi][ni][h * 2 + 0];
                float c1 = acc[mi][ni][h * 2 + 1];
                ds += c0 * att_sh[col] + c1 * att_sh[col + 1];
                dd += c0 * att_sh[128 + col] + c1 * att_sh[128 + col + 1];
            }
            ds += __shfl_xor_sync(0xffffffffu, ds, 1);
            ds += __shfl_xor_sync(0xffffffffu, ds, 2);
            dd += __shfl_xor_sync(0xffffffffu, dd, 1);
            dd += __shfl_xor_sync(0xffffffffu, dd, 2);
            if (t == 0) {
                int rl = warp_m + mi * 16 + g + h * 8;   // 0..63
                atomicAdd(&sdot[rl], ds);
                atomicAdd(&sdot[64 + rl], dd);
            }
        }
    }
    __syncthreads();
    if (tid < 64) {
        int gr = row0 + tid;
        if (gr < N) {
            g_asrc[gr] = sdot[tid];
            g_adst[gr] = sdot[64 + tid];
            g_hist[gr] = 1;      // self loop
            g_maxkey[gr] = 0u;
        }
    }
}

// ---------------- 2) histogram of dst (4 edges/thread for MLP) ----------------
__global__ void k_hist(const void* __restrict__ ei, int E) {
    int base = (blockIdx.x * blockDim.x + threadIdx.x) * 4;
    int is64 = g_is64;
    #pragma unroll
    for (int q = 0; q < 4; ++q) {
        int e = base + q;
        if (e < E) atomicAdd(&g_hist[edge_at(ei, E + e, is64)], 1);
    }
}

// ---------------- 3a) per-tile exclusive scan ----------------
__global__ void k_scanA(int N) {
    __shared__ int wsum[8];
    __shared__ int blktot;
    const int tid = threadIdx.x;
    const int lane = tid & 31, wid = tid >> 5;
    const int i0 = blockIdx.x * SCAN_TILE + tid * 4;

    int v0 = 0, v1 = 0, v2 = 0, v3 = 0;
    if (i0 + 3 < N) {
        int4 v = *(const int4*)&g_hist[i0];
        v0 = v.x; v1 = v.y; v2 = v.z; v3 = v.w;
    } else {
        if (i0 < N)     v0 = g_hist[i0];
        if (i0 + 1 < N) v1 = g_hist[i0 + 1];
        if (i0 + 2 < N) v2 = g_hist[i0 + 2];
        if (i0 + 3 < N) v3 = g_hist[i0 + 3];
    }
    int s0 = v0, s1 = s0 + v1, s2 = s1 + v2, s3 = s2 + v3;
    int tsum = s3;
    int incl = tsum;
    #pragma unroll
    for (int off = 1; off < 32; off <<= 1) {
        int n = __shfl_up_sync(0xffffffffu, incl, off);
        if (lane >= off) incl += n;
    }
    if (lane == 31) wsum[wid] = incl;
    __syncthreads();
    if (wid == 0 && lane < 8) {
        int wv = wsum[lane];
        int wi = wv;
        #pragma unroll
        for (int off = 1; off < 8; off <<= 1) {
            int n = __shfl_up_sync(0xffu, wi, off);
            if (lane >= off) wi += n;
        }
        wsum[lane] = wi - wv;
        if (lane == 7) blktot = wi;
    }
    __syncthreads();
    int base = wsum[wid] + (incl - tsum);
    if (i0 < N)     g_rowstart[i0]     = base;
    if (i0 + 1 < N) g_rowstart[i0 + 1] = base + s0;
    if (i0 + 2 < N) g_rowstart[i0 + 2] = base + s1;
    if (i0 + 3 < N) g_rowstart[i0 + 3] = base + s2;
    if (tid == 0) g_bsum[blockIdx.x] = blktot;
}

// ---------------- 3b) scan of block totals ----------------
__global__ void k_scanB(int nblk) {
    __shared__ int sp[MAXBLK];
    int tid = threadIdx.x;
    int v = (tid < nblk) ? g_bsum[tid] : 0;
    sp[tid] = v;
    __syncthreads();
    for (int off = 1; off < MAXBLK; off <<= 1) {
        int n = (tid >= off) ? sp[tid - off] : 0;
        __syncthreads();
        sp[tid] += n;
        __syncthreads();
    }
    if (tid < nblk) g_boff[tid] = sp[tid] - v;
}

// ---------------- 3c) apply block offsets ----------------
__global__ void k_scanC(int N, int totalEN) {
    int i = blockIdx.x * blockDim.x + threadIdx.x;
    if (i < N) {
        int r = g_rowstart[i] + g_boff[i >> 10];
        g_rowstart[i] = r;
        g_cursor[i]   = r;
    }
    if (i == 0) g_rowstart[N] = totalEN;
}

// ---------------- 4) scatter: group by dst + logits + segment max ----------------
__global__ void k_scatter(const void* __restrict__ ei, int N, int E) {
    int idx = blockIdx.x * blockDim.x + threadIdx.x;
    int is64 = g_is64;
    if (idx < E) {
        int d = edge_at(ei, E + idx, is64);
        int s = edge_at(ei, idx, is64);
        float e = g_asrc[s] + g_adst[d];
        e = (e >= 0.f) ? e : 0.2f * e;
        int pos = atomicAdd(&g_cursor[d], 1);
        g_edge[pos] = make_int2(s, __float_as_int(e));
        atomicMax(&g_maxkey[d], fkey(e));
    } else if (idx < E + N) {
        int i = idx - E;
        float e = g_asrc[i] + g_adst[i];
        e = (e >= 0.f) ? e : 0.2f * e;
        int pos = atomicAdd(&g_cursor[i], 1);
        g_edge[pos] = make_int2(i, __float_as_int(e));
        atomicMax(&g_maxkey[i], fkey(e));
    }
}

// ---------------- 5) fused softmax + gather: one WARP per dst node ----------------
__global__ void k_agg(const float* __restrict__ bias, float* __restrict__ out, int N) {
    const int gw = (blockIdx.x * blockDim.x + threadIdx.x) >> 5;
    const int lane = threadIdx.x & 31;
    if (gw >= N) return;

    const int beg = g_rowstart[gw];
    const int end = g_rowstart[gw + 1];
    const float m = funkey(g_maxkey[gw]);

    float4 acc = make_float4(0.f, 0.f, 0.f, 0.f);
    float sum = 0.f;

    for (int c = beg; c < end; c += 32) {
        int j = c + lane;
        int src = 0;
        float w = 0.f;
        if (j < end) {
            int2 ed = g_edge[j];
            src = ed.x;
            w = __expf(__int_as_float(ed.y) - m);
        }
        float ws = w;
        #pragma unroll
        for (int o = 16; o > 0; o >>= 1) ws += __shfl_xor_sync(0xffffffffu, ws, o);
        sum += ws;

        int cnt = min(32, end - c);
        for (int jj = 0; jj < cnt; ++jj) {
            float wj = __shfl_sync(0xffffffffu, w, jj);
            int   sj = __shfl_sync(0xffffffffu, src, jj);
            float4 v = ((const float4*)(g_xp + (size_t)sj * 128))[lane];
            acc.x += wj * v.x; acc.y += wj * v.y;
            acc.z += wj * v.z; acc.w += wj * v.w;
        }
    }

    const float inv = 1.f / sum;
    float4 b4 = ((const float4*)bias)[lane];
    ((float4*)(out + (size_t)gw * 128))[lane] =
        make_float4(acc.x * inv + b4.x, acc.y * inv + b4.y,
                    acc.z * inv + b4.z, acc.w * inv + b4.w);
}

// ---------------- launch ----------------
extern "C" void kernel_launch(void* const* d_in, const int* in_sizes, int n_in,
                              void* d_out, int out_size) {
    const float* x        = (const float*)d_in[0];
    const float* W        = (const float*)d_in[1];
    const float* att_src  = (const float*)d_in[2];
    const float* att_dst  = (const float*)d_in[3];
    const float* bias     = (const float*)d_in[4];
    const void*  ei       = d_in[5];

    const int N = in_sizes[0] / F;
    const int E = in_sizes[5] / 2;
    const int nblk = (N + SCAN_TILE - 1) / SCAN_TILE;
    float* out = (float*)d_out;

    k_detect <<<1, 256>>>((const int*)ei, E);
    k_gemm   <<<(N + 63) / 64, 256>>>(x, W, att_src, att_dst, N);
    k_hist   <<<(E + 1023) / 1024, 256>>>(ei, E);
    k_scanA  <<<nblk, 256>>>(N);
    k_scanB  <<<1, MAXBLK>>>(nblk);
    k_scanC  <<<(N + 255) / 256, 256>>>(N, E + N);
    k_scatter<<<(E + N + 255) / 256, 256>>>(ei, N, E);
    k_agg    <<<(N + 7) / 8, 256>>>(bias, out, N);
}

// round 9
// speedup vs baseline: 2.5751x; 1.0646x over previous
#include <cuda_runtime.h>
#include <cstdint>

#define F 128
#define NMAX 65536
#define EMAX 1200000
#define SCAN_TILE 1024
#define MAXBLK (NMAX / SCAN_TILE)   // 64
#define XS_STRIDE 132
#define WS_STRIDE 136

// ---------------- scratch (no allocations allowed) ----------------
__device__ float    g_xp[NMAX * F];
__device__ float    g_asrc[NMAX];
__device__ float    g_adst[NMAX];
__device__ int      g_hist[NMAX];          // edge-only in-degree (self loop added in scan)
__device__ int      g_rowstart[NMAX + 1];
__device__ int      g_cursor[NMAX];
__device__ int      g_bsum[MAXBLK];
__device__ int      g_boff[MAXBLK];
__device__ int2     g_edge[EMAX];
__device__ unsigned g_maxkey[NMAX];
__device__ int      g_is64;

__device__ __forceinline__ int edge_at(const void* ei, int idx, int is64) {
    if (is64) return (int)((const long long*)ei)[idx];
    return ((const int*)ei)[idx];
}

__device__ __forceinline__ unsigned fkey(float f) {
    int i = __float_as_int(f);
    return (i >= 0) ? ((unsigned)i | 0x80000000u) : (unsigned)(~i);
}
__device__ __forceinline__ float funkey(unsigned u) {
    int i = (u & 0x80000000u) ? (int)(u ^ 0x80000000u) : (int)(~u);
    return __int_as_float(i);
}

// ---- tf32 helpers ----
__device__ __forceinline__ uint32_t cvt_tf32(float a) {
    uint32_t r;
    asm("cvt.rna.tf32.f32 %0, %1;" : "=r"(r) : "f"(a));
    return r;
}
__device__ __forceinline__ void split_tf32(float a, uint32_t& hi, uint32_t& lo) {
    hi = cvt_tf32(a);
    lo = cvt_tf32(a - __uint_as_float(hi));
}
__device__ __forceinline__ void mma_tf32(float* d, const uint32_t* a, const uint32_t* b) {
    asm volatile(
        "mma.sync.aligned.m16n8k8.row.col.f32.tf32.tf32.f32 "
        "{%0,%1,%2,%3}, {%4,%5,%6,%7}, {%8,%9}, {%0,%1,%2,%3};\n"
        : "+f"(d[0]), "+f"(d[1]), "+f"(d[2]), "+f"(d[3])
        : "r"(a[0]), "r"(a[1]), "r"(a[2]), "r"(a[3]), "r"(b[0]), "r"(b[1]));
}

// ---------------- 0) dtype detection ----------------
__global__ void k_detect(const int* __restrict__ ei32, int E) {
    __shared__ int any;
    if (threadIdx.x == 0) any = 0;
    __syncthreads();
    int total = 2 * E;
    int stride = (total / 2) / 4096;
    if (stride < 1) stride = 1;
    for (int q = threadIdx.x; q < 4096; q += blockDim.x) {
        long long w = 1 + 2 * (long long)q * stride;
        if (w < total && ei32[w] != 0) { any = 1; break; }
    }
    __syncthreads();
    if (threadIdx.x == 0) g_is64 = (any == 0) ? 1 : 0;
}

// ---------------- 1) TF32 tensor GEMM xp = x@W (+ fused attention logits) ----------------
__global__ void k_gemm(const float* __restrict__ x, const float* __restrict__ W,
                       const float* __restrict__ att_src, const float* __restrict__ att_dst,
                       int N) {
    __shared__ float xs[64 * XS_STRIDE];
    __shared__ float ws[16 * WS_STRIDE];
    __shared__ float att_sh[256];
    __shared__ float sdot[128];

    const int tid  = threadIdx.x;           // 256
    const int lane = tid & 31;
    const int w    = tid >> 5;
    const int g    = lane >> 2;
    const int t    = lane & 3;
    const int warp_m = (w & 1) * 32;
    const int warp_n = (w >> 1) * 32;
    const int row0 = blockIdx.x * 64;

    if (tid < 128) {
        att_sh[tid]       = att_src[tid];
        att_sh[128 + tid] = att_dst[tid];
        sdot[tid] = 0.f;
    }

    {   // load x tile (full K), zero-pad tail rows
        const float4* x4 = (const float4*)x;
        float4* xs4 = (float4*)xs;
        #pragma unroll
        for (int q = 0; q < 8; ++q) {
            int fi = q * 256 + tid;
            int r = fi >> 5, c4 = fi & 31;
            int gr = row0 + r;
            float4 v = make_float4(0.f, 0.f, 0.f, 0.f);
            if (gr < N) v = x4[gr * 32 + c4];
            xs4[r * (XS_STRIDE / 4) + c4] = v;
        }
    }

    float acc[2][4][4];
    #pragma unroll
    for (int mi = 0; mi < 2; ++mi)
        #pragma unroll
        for (int ni = 0; ni < 4; ++ni)
            #pragma unroll
            for (int q = 0; q < 4; ++q) acc[mi][ni][q] = 0.f;

    for (int kt = 0; kt < 8; ++kt) {
        __syncthreads();
        {
            const float4* W4 = (const float4*)W;
            float4* ws4 = (float4*)ws;
            #pragma unroll
            for (int q = 0; q < 2; ++q) {
                int fi = q * 256 + tid;
                int r = fi >> 5, c4 = fi & 31;
                ws4[r * (WS_STRIDE / 4) + c4] = W4[(kt * 16 + r) * 32 + c4];
            }
        }
        __syncthreads();
        #pragma unroll
        for (int ks = 0; ks < 2; ++ks) {
            const int kk = ks * 8;
            uint32_t aHi[2][4], aLo[2][4];
            #pragma unroll
            for (int mi = 0; mi < 2; ++mi) {
                int r0 = warp_m + mi * 16 + g;
                int kc = kt * 16 + kk + t;
                split_tf32(xs[r0 * XS_STRIDE + kc],           aHi[mi][0], aLo[mi][0]);
                split_tf32(xs[(r0 + 8) * XS_STRIDE + kc],     aHi[mi][1], aLo[mi][1]);
                split_tf32(xs[r0 * XS_STRIDE + kc + 4],       aHi[mi][2], aLo[mi][2]);
                split_tf32(xs[(r0 + 8) * XS_STRIDE + kc + 4], aHi[mi][3], aLo[mi][3]);
            }
            uint32_t bHi[4][2], bLo[4][2];
            #pragma unroll
            for (int ni = 0; ni < 4; ++ni) {
                int nc = warp_n + ni * 8 + g;
                split_tf32(ws[(kk + t) * WS_STRIDE + nc],     bHi[ni][0], bLo[ni][0]);
                split_tf32(ws[(kk + t + 4) * WS_STRIDE + nc], bHi[ni][1], bLo[ni][1]);
            }
            #pragma unroll
            for (int mi = 0; mi < 2; ++mi)
                #pragma unroll
                for (int ni = 0; ni < 4; ++ni) {
                    mma_tf32(acc[mi][ni], aHi[mi], bHi[ni]);
                    mma_tf32(acc[mi][ni], aLo[mi], bHi[ni]);
                    mma_tf32(acc[mi][ni], aHi[mi], bLo[ni]);
                }
        }
    }

    #pragma unroll
    for (int mi = 0; mi < 2; ++mi) {
        int gr = row0 + warp_m + mi * 16 + g;
        #pragma unroll
        for (int ni = 0; ni < 4; ++ni) {
            int col = warp_n + ni * 8 + 2 * t;
            if (gr < N)
                *(float2*)&g_xp[(size_t)gr * 128 + col] =
                    make_float2(acc[mi][ni][0], acc[mi][ni][1]);
            if (gr + 8 < N)
                *(float2*)&g_xp[(size_t)(gr + 8) * 128 + col] =
                    make_float2(acc[mi][ni][2], acc[mi][ni][3]);
        }
    }

    #pragma unroll
    for (int mi = 0; mi < 2; ++mi) {
        #pragma unroll
        for (int h = 0; h < 2; ++h) {
            float ds = 0.f, dd = 0.f;
            #pragma unroll
            for (int ni = 0; ni < 4; ++ni) {
                int col = warp_n + ni * 8 + 2 * t;
                float c0 = acc[mi][ni][h * 2 + 0];
                float c1 = acc[mi][ni][h * 2 + 1];
                ds += c0 * att_sh[col] + c1 * att_sh[col + 1];
                dd += c0 * att_sh[128 + col] + c1 * att_sh[128 + col + 1];
            }
            ds += __shfl_xor_sync(0xffffffffu, ds, 1);
            ds += __shfl_xor_sync(0xffffffffu, ds, 2);
            dd += __shfl_xor_sync(0xffffffffu, dd, 1);
            dd += __shfl_xor_sync(0xffffffffu, dd, 2);
            if (t == 0) {
                int rl = warp_m + mi * 16 + g + h * 8;
                atomicAdd(&sdot[rl], ds);
                atomicAdd(&sdot[64 + rl], dd);
            }
        }
    }
    __syncthreads();
    if (tid < 64) {
        int gr = row0 + tid;
        if (gr < N) {
            g_asrc[gr] = sdot[tid];
            g_adst[gr] = sdot[64 + tid];
            g_maxkey[gr] = 0u;
        }
    }
}

// ---------------- 2) histogram of dst (edges only; hist pre-zeroed) ----------------
__global__ void k_hist(const void* __restrict__ ei, int E) {
    int base = (blockIdx.x * blockDim.x + threadIdx.x) * 4;
    int is64 = g_is64;
    #pragma unroll
    for (int q = 0; q < 4; ++q) {
        int e = base + q;
        if (e < E) atomicAdd(&g_hist[edge_at(ei, E + e, is64)], 1);
    }
}

// ---------------- 3a) per-tile exclusive scan of (hist[i] + 1) ----------------
__global__ void k_scanA(int N) {
    __shared__ int wsum[8];
    __shared__ int blktot;
    const int tid = threadIdx.x;
    const int lane = tid & 31, wid = tid >> 5;
    const int i0 = blockIdx.x * SCAN_TILE + tid * 4;

    int v0 = 0, v1 = 0, v2 = 0, v3 = 0;
    if (i0 + 3 < N) {
        int4 v = *(const int4*)&g_hist[i0];
        v0 = v.x + 1; v1 = v.y + 1; v2 = v.z + 1; v3 = v.w + 1;   // +1 self loop
    } else {
        if (i0 < N)     v0 = g_hist[i0] + 1;
        if (i0 + 1 < N) v1 = g_hist[i0 + 1] + 1;
        if (i0 + 2 < N) v2 = g_hist[i0 + 2] + 1;
        if (i0 + 3 < N) v3 = g_hist[i0 + 3] + 1;
    }
    int s0 = v0, s1 = s0 + v1, s2 = s1 + v2, s3 = s2 + v3;
    int tsum = s3;
    int incl = tsum;
    #pragma unroll
    for (int off = 1; off < 32; off <<= 1) {
        int n = __shfl_up_sync(0xffffffffu, incl, off);
        if (lane >= off) incl += n;
    }
    if (lane == 31) wsum[wid] = incl;
    __syncthreads();
    if (wid == 0 && lane < 8) {
        int wv = wsum[lane];
        int wi = wv;
        #pragma unroll
        for (int off = 1; off < 8; off <<= 1) {
            int n = __shfl_up_sync(0xffu, wi, off);
            if (lane >= off) wi += n;
        }
        wsum[lane] = wi - wv;
        if (lane == 7) blktot = wi;
    }
    __syncthreads();
    int base = wsum[wid] + (incl - tsum);
    if (i0 < N)     g_rowstart[i0]     = base;
    if (i0 + 1 < N) g_rowstart[i0 + 1] = base + s0;
    if (i0 + 2 < N) g_rowstart[i0 + 2] = base + s1;
    if (i0 + 3 < N) g_rowstart[i0 + 3] = base + s2;
    if (tid == 0) g_bsum[blockIdx.x] = blktot;
}

// ---------------- 3b) scan of block totals ----------------
__global__ void k_scanB(int nblk) {
    __shared__ int sp[MAXBLK];
    int tid = threadIdx.x;
    int v = (tid < nblk) ? g_bsum[tid] : 0;
    sp[tid] = v;
    __syncthreads();
    for (int off = 1; off < MAXBLK; off <<= 1) {
        int n = (tid >= off) ? sp[tid - off] : 0;
        __syncthreads();
        sp[tid] += n;
        __syncthreads();
    }
    if (tid < nblk) g_boff[tid] = sp[tid] - v;
}

// ---------------- 3c) apply block offsets ----------------
__global__ void k_scanC(int N, int totalEN) {
    int i = blockIdx.x * blockDim.x + threadIdx.x;
    if (i < N) {
        int r = g_rowstart[i] + g_boff[i >> 10];
        g_rowstart[i] = r;
        g_cursor[i]   = r;
    }
    if (i == 0) g_rowstart[N] = totalEN;
}

// ---------------- 4) scatter: group by dst + logits + segment max ----------------
__global__ void k_scatter(const void* __restrict__ ei, int N, int E) {
    int idx = blockIdx.x * blockDim.x + threadIdx.x;
    int is64 = g_is64;
    if (idx < E) {
        int d = edge_at(ei, E + idx, is64);
        int s = edge_at(ei, idx, is64);
        float e = g_asrc[s] + g_adst[d];
        e = (e >= 0.f) ? e : 0.2f * e;
        int pos = atomicAdd(&g_cursor[d], 1);
        g_edge[pos] = make_int2(s, __float_as_int(e));
        atomicMax(&g_maxkey[d], fkey(e));
    } else if (idx < E + N) {
        int i = idx - E;
        float e = g_asrc[i] + g_adst[i];
        e = (e >= 0.f) ? e : 0.2f * e;
        int pos = atomicAdd(&g_cursor[i], 1);
        g_edge[pos] = make_int2(i, __float_as_int(e));
        atomicMax(&g_maxkey[i], fkey(e));
    }
}

// ---------------- 5) fused softmax + gather: one WARP per dst node ----------------
__global__ void k_agg(const float* __restrict__ bias, float* __restrict__ out, int N) {
    const int gw = (blockIdx.x * blockDim.x + threadIdx.x) >> 5;
    const int lane = threadIdx.x & 31;
    if (gw >= N) return;

    const int beg = g_rowstart[gw];
    const int end = g_rowstart[gw + 1];
    const float m = funkey(g_maxkey[gw]);

    float4 acc = make_float4(0.f, 0.f, 0.f, 0.f);
    float sum = 0.f;

    for (int c = beg; c < end; c += 32) {
        int j = c + lane;
        int src = 0;
        float w = 0.f;
        if (j < end) {
            int2 ed = g_edge[j];
            src = ed.x;
            w = __expf(__int_as_float(ed.y) - m);
        }
        float ws = w;
        #pragma unroll
        for (int o = 16; o > 0; o >>= 1) ws += __shfl_xor_sync(0xffffffffu, ws, o);
        sum += ws;

        int cnt = min(32, end - c);
        if (cnt == 32) {
            #pragma unroll 8
            for (int jj = 0; jj < 32; ++jj) {
                float wj = __shfl_sync(0xffffffffu, w, jj);
                int   sj = __shfl_sync(0xffffffffu, src, jj);
                float4 v = ((const float4*)(g_xp + (size_t)sj * 128))[lane];
                acc.x += wj * v.x; acc.y += wj * v.y;
                acc.z += wj * v.z; acc.w += wj * v.w;
            }
        } else {
            for (int jj = 0; jj < cnt; ++jj) {
                float wj = __shfl_sync(0xffffffffu, w, jj);
                int   sj = __shfl_sync(0xffffffffu, src, jj);
                float4 v = ((const float4*)(g_xp + (size_t)sj * 128))[lane];
                acc.x += wj * v.x; acc.y += wj * v.y;
                acc.z += wj * v.z; acc.w += wj * v.w;
            }
        }
    }

    const float inv = 1.f / sum;
    float4 b4 = ((const float4*)bias)[lane];
    ((float4*)(out + (size_t)gw * 128))[lane] =
        make_float4(acc.x * inv + b4.x, acc.y * inv + b4.y,
                    acc.z * inv + b4.z, acc.w * inv + b4.w);
}

// ---------------- launch (fork-join: edge prep overlaps GEMM) ----------------
extern "C" void kernel_launch(void* const* d_in, const int* in_sizes, int n_in,
                              void* d_out, int out_size) {
    const float* x        = (const float*)d_in[0];
    const float* W        = (const float*)d_in[1];
    const float* att_src  = (const float*)d_in[2];
    const float* att_dst  = (const float*)d_in[3];
    const float* bias     = (const float*)d_in[4];
    const void*  ei       = d_in[5];

    const int N = in_sizes[0] / F;
    const int E = in_sizes[5] / 2;
    const int nblk = (N + SCAN_TILE - 1) / SCAN_TILE;
    float* out = (float*)d_out;

    static cudaStream_t s1 = nullptr;
    static cudaEvent_t e0 = nullptr, e1 = nullptr;
    static void* hist_addr = nullptr;
    if (s1 == nullptr) {
        cudaStreamCreateWithFlags(&s1, cudaStreamNonBlocking);
        cudaEventCreateWithFlags(&e0, cudaEventDisableTiming);
        cudaEventCreateWithFlags(&e1, cudaEventDisableTiming);
        cudaGetSymbolAddress(&hist_addr, g_hist);
    }

    // fork: s1 handles the edge-prep chain (independent of GEMM)
    cudaEventRecord(e0, 0);
    cudaStreamWaitEvent(s1, e0, 0);
    cudaMemsetAsync(hist_addr, 0, (size_t)N * sizeof(int), s1);
    k_detect <<<1, 256, 0, s1>>>((const int*)ei, E);
    k_hist   <<<(E + 1023) / 1024, 256, 0, s1>>>(ei, E);
    k_scanA  <<<nblk, 256, 0, s1>>>(N);
    k_scanB  <<<1, MAXBLK, 0, s1>>>(nblk);
    k_scanC  <<<(N + 255) / 256, 256, 0, s1>>>(N, E + N);
    cudaEventRecord(e1, s1);

    // main stream: GEMM in parallel with the prep chain
    k_gemm   <<<(N + 63) / 64, 256>>>(x, W, att_src, att_dst, N);

    // join, then edge scatter + aggregation
    cudaStreamWaitEvent(0, e1, 0);
    k_scatter<<<(E + N + 255) / 256, 256>>>(ei, N, E);
    k_agg    <<<(N + 7) / 8, 256>>>(bias, out, N);
}

// round 10
// speedup vs baseline: 2.5904x; 1.0059x over previous
#include <cuda_runtime.h>
#include <cuda_bf16.h>
#include <cstdint>

#define F 128
#define NMAX 65536
#define EMAX 1200000
#define SCAN_TILE 1024
#define MAXBLK (NMAX / SCAN_TILE)   // 64
#define XS2 136                     // bf16 stride; word stride 68 -> (4g+t) banks, conflict-free

// ---------------- scratch (no allocations allowed) ----------------
__device__ float          g_xp[NMAX * F];
__device__ float          g_asrc[NMAX];
__device__ float          g_adst[NMAX];
__device__ int            g_hist[NMAX];
__device__ int            g_rowstart[NMAX + 1];
__device__ int            g_cursor[NMAX];
__device__ int            g_bsum[MAXBLK];
__device__ int            g_boff[MAXBLK];
__device__ int2           g_edge[EMAX];
__device__ unsigned       g_maxkey[NMAX];
__device__ int            g_is64;
__device__ __nv_bfloat16  g_whi[128 * 128];   // W^T split-hi, [n][k]
__device__ __nv_bfloat16  g_wlo[128 * 128];   // W^T split-lo, [n][k]

__device__ __forceinline__ int edge_at(const void* ei, int idx, int is64) {
    if (is64) return (int)((const long long*)ei)[idx];
    return ((const int*)ei)[idx];
}

__device__ __forceinline__ unsigned fkey(float f) {
    int i = __float_as_int(f);
    return (i >= 0) ? ((unsigned)i | 0x80000000u) : (unsigned)(~i);
}
__device__ __forceinline__ float funkey(unsigned u) {
    int i = (u & 0x80000000u) ? (int)(u ^ 0x80000000u) : (int)(~u);
    return __int_as_float(i);
}

__device__ __forceinline__ void mma_bf16(float* d, const uint32_t* a, const uint32_t* b) {
    asm volatile(
        "mma.sync.aligned.m16n8k16.row.col.f32.bf16.bf16.f32 "
        "{%0,%1,%2,%3}, {%4,%5,%6,%7}, {%8,%9}, {%0,%1,%2,%3};\n"
        : "+f"(d[0]), "+f"(d[1]), "+f"(d[2]), "+f"(d[3])
        : "r"(a[0]), "r"(a[1]), "r"(a[2]), "r"(a[3]), "r"(b[0]), "r"(b[1]));
}

// ---------------- 0) dtype detection ----------------
__global__ void k_detect(const int* __restrict__ ei32, int E) {
    __shared__ int any;
    if (threadIdx.x == 0) any = 0;
    __syncthreads();
    int total = 2 * E;
    int stride = (total / 2) / 4096;
    if (stride < 1) stride = 1;
    for (int q = threadIdx.x; q < 4096; q += blockDim.x) {
        long long w = 1 + 2 * (long long)q * stride;
        if (w < total && ei32[w] != 0) { any = 1; break; }
    }
    __syncthreads();
    if (threadIdx.x == 0) g_is64 = (any == 0) ? 1 : 0;
}

// ---------------- 0b) split + transpose W -> bf16 hi/lo [n][k] ----------------
__global__ void k_wsplit(const float* __restrict__ W) {
    int idx = blockIdx.x * blockDim.x + threadIdx.x;   // 16384
    int k = idx >> 7, n = idx & 127;
    float a = W[idx];                                  // W[k][n], coalesced read
    __nv_bfloat16 hi = __float2bfloat16_rn(a);
    __nv_bfloat16 lo = __float2bfloat16_rn(a - __bfloat162float(hi));
    g_whi[n * 128 + k] = hi;
    g_wlo[n * 128 + k] = lo;
}

// ---------------- 1) BF16 split tensor GEMM xp = x@W (+ fused attention logits) ----------------
// block tile 64x128x128; 8 warps, warp tile 32x32; acc += aHi*bHi + aLo*bHi + aHi*bLo
__global__ void k_gemm(const float* __restrict__ x,
                       const float* __restrict__ att_src, const float* __restrict__ att_dst,
                       int N) {
    __shared__ __nv_bfloat16 xs_hi[64 * XS2];   // 17408 B
    __shared__ __nv_bfloat16 xs_lo[64 * XS2];   // 17408 B
    __shared__ float att_sh[256];
    __shared__ float sdot[128];

    const int tid  = threadIdx.x;               // 256
    const int lane = tid & 31;
    const int w    = tid >> 5;
    const int g    = lane >> 2;                 // 0..7
    const int t    = lane & 3;                  // 0..3
    const int warp_m = (w & 1) * 32;
    const int warp_n = (w >> 1) * 32;
    const int row0 = blockIdx.x * 64;

    if (tid < 128) {
        att_sh[tid]       = att_src[tid];
        att_sh[128 + tid] = att_dst[tid];
        sdot[tid] = 0.f;
    }

    {   // load + split x tile into bf16 hi/lo planes
        const float4* x4 = (const float4*)x;
        #pragma unroll
        for (int q = 0; q < 8; ++q) {
            int fi = q * 256 + tid;             // 0..2047
            int r = fi >> 5, c4 = fi & 31;
            int gr = row0 + r;
            float4 v = make_float4(0.f, 0.f, 0.f, 0.f);
            if (gr < N) v = x4[gr * 32 + c4];
            __nv_bfloat16 h0 = __float2bfloat16_rn(v.x);
            __nv_bfloat16 h1 = __float2bfloat16_rn(v.y);
            __nv_bfloat16 h2 = __float2bfloat16_rn(v.z);
            __nv_bfloat16 h3 = __float2bfloat16_rn(v.w);
            __nv_bfloat16 l0 = __float2bfloat16_rn(v.x - __bfloat162float(h0));
            __nv_bfloat16 l1 = __float2bfloat16_rn(v.y - __bfloat162float(h1));
            __nv_bfloat16 l2 = __float2bfloat16_rn(v.z - __bfloat162float(h2));
            __nv_bfloat16 l3 = __float2bfloat16_rn(v.w - __bfloat162float(h3));
            int off = r * XS2 + c4 * 4;
            *(__nv_bfloat162*)&xs_hi[off]     = __nv_bfloat162(h0, h1);
            *(__nv_bfloat162*)&xs_hi[off + 2] = __nv_bfloat162(h2, h3);
            *(__nv_bfloat162*)&xs_lo[off]     = __nv_bfloat162(l0, l1);
            *(__nv_bfloat162*)&xs_lo[off + 2] = __nv_bfloat162(l2, l3);
        }
    }

    float acc[2][4][4];
    #pragma unroll
    for (int mi = 0; mi < 2; ++mi)
        #pragma unroll
        for (int ni = 0; ni < 4; ++ni)
            #pragma unroll
            for (int q = 0; q < 4; ++q) acc[mi][ni][q] = 0.f;

    __syncthreads();

    #pragma unroll
    for (int kt = 0; kt < 8; ++kt) {
        const int k0 = kt * 16 + 2 * t;
        // A fragments (a0:(g,2t..) a1:(g+8) a2:(g,2t+8..) a3:(g+8,2t+8..))
        uint32_t aHi[2][4], aLo[2][4];
        #pragma unroll
        for (int mi = 0; mi < 2; ++mi) {
            int r0 = warp_m + mi * 16 + g;
            aHi[mi][0] = *(const uint32_t*)&xs_hi[r0 * XS2 + k0];
            aHi[mi][1] = *(const uint32_t*)&xs_hi[(r0 + 8) * XS2 + k0];
            aHi[mi][2] = *(const uint32_t*)&xs_hi[r0 * XS2 + k0 + 8];
            aHi[mi][3] = *(const uint32_t*)&xs_hi[(r0 + 8) * XS2 + k0 + 8];
            aLo[mi][0] = *(const uint32_t*)&xs_lo[r0 * XS2 + k0];
            aLo[mi][1] = *(const uint32_t*)&xs_lo[(r0 + 8) * XS2 + k0];
            aLo[mi][2] = *(const uint32_t*)&xs_lo[r0 * XS2 + k0 + 8];
            aLo[mi][3] = *(const uint32_t*)&xs_lo[(r0 + 8) * XS2 + k0 + 8];
        }
        // B fragments from global bf16 W^T (L1-resident): b0:(2t,n) b1:(2t+8,n)
        uint32_t bHi[4][2], bLo[4][2];
        #pragma unroll
        for (int ni = 0; ni < 4; ++ni) {
            int base = (warp_n + ni * 8 + g) * 128 + k0;
            bHi[ni][0] = *(const uint32_t*)&g_whi[base];
            bHi[ni][1] = *(const uint32_t*)&g_whi[base + 8];
            bLo[ni][0] = *(const uint32_t*)&g_wlo[base];
            bLo[ni][1] = *(const uint32_t*)&g_wlo[base + 8];
        }
        #pragma unroll
        for (int mi = 0; mi < 2; ++mi)
            #pragma unroll
            for (int ni = 0; ni < 4; ++ni) {
                mma_bf16(acc[mi][ni], aHi[mi], bHi[ni]);
                mma_bf16(acc[mi][ni], aLo[mi], bHi[ni]);
                mma_bf16(acc[mi][ni], aHi[mi], bLo[ni]);
            }
    }

    // ---- write xp (c0:(g,2t) c1:(g,2t+1) c2:(g+8,2t) c3:(g+8,2t+1)) ----
    #pragma unroll
    for (int mi = 0; mi < 2; ++mi) {
        int gr = row0 + warp_m + mi * 16 + g;
        #pragma unroll
        for (int ni = 0; ni < 4; ++ni) {
            int col = warp_n + ni * 8 + 2 * t;
            if (gr < N)
                *(float2*)&g_xp[(size_t)gr * 128 + col] =
                    make_float2(acc[mi][ni][0], acc[mi][ni][1]);
            if (gr + 8 < N)
                *(float2*)&g_xp[(size_t)(gr + 8) * 128 + col] =
                    make_float2(acc[mi][ni][2], acc[mi][ni][3]);
        }
    }

    // ---- fused attention logits ----
    #pragma unroll
    for (int mi = 0; mi < 2; ++mi) {
        #pragma unroll
        for (int h = 0; h < 2; ++h) {
            float ds = 0.f, dd = 0.f;
            #pragma unroll
            for (int ni = 0; ni < 4; ++ni) {
                int col = warp_n + ni * 8 + 2 * t;
                float c0 = acc[mi][ni][h * 2 + 0];
                float c1 = acc[mi][ni][h * 2 + 1];
                ds += c0 * att_sh[col] + c1 * att_sh[col + 1];
                dd += c0 * att_sh[128 + col] + c1 * att_sh[128 + col + 1];
            }
            ds += __shfl_xor_sync(0xffffffffu, ds, 1);
            ds += __shfl_xor_sync(0xffffffffu, ds, 2);
            dd += __shfl_xor_sync(0xffffffffu, dd, 1);
            dd += __shfl_xor_sync(0xffffffffu, dd, 2);
            if (t == 0) {
                int rl = warp_m + mi * 16 + g + h * 8;
                atomicAdd(&sdot[rl], ds);
                atomicAdd(&sdot[64 + rl], dd);
            }
        }
    }
    __syncthreads();
    if (tid < 64) {
        int gr = row0 + tid;
        if (gr < N) {
            g_asrc[gr] = sdot[tid];
            g_adst[gr] = sdot[64 + tid];
            g_maxkey[gr] = 0u;
        }
    }
}

// ---------------- 2) histogram of dst (edges only; hist pre-zeroed) ----------------
__global__ void k_hist(const void* __restrict__ ei, int E) {
    int base = (blockIdx.x * blockDim.x + threadIdx.x) * 4;
    int is64 = g_is64;
    #pragma unroll
    for (int q = 0; q < 4; ++q) {
        int e = base + q;
        if (e < E) atomicAdd(&g_hist[edge_at(ei, E + e, is64)], 1);
    }
}

// ---------------- 3a) per-tile exclusive scan of (hist[i] + 1) ----------------
__global__ void k_scanA(int N) {
    __shared__ int wsum[8];
    __shared__ int blktot;
    const int tid = threadIdx.x;
    const int lane = tid & 31, wid = tid >> 5;
    const int i0 = blockIdx.x * SCAN_TILE + tid * 4;

    int v0 = 0, v1 = 0, v2 = 0, v3 = 0;
    if (i0 + 3 < N) {
        int4 v = *(const int4*)&g_hist[i0];
        v0 = v.x + 1; v1 = v.y + 1; v2 = v.z + 1; v3 = v.w + 1;
    } else {
        if (i0 < N)     v0 = g_hist[i0] + 1;
        if (i0 + 1 < N) v1 = g_hist[i0 + 1] + 1;
        if (i0 + 2 < N) v2 = g_hist[i0 + 2] + 1;
        if (i0 + 3 < N) v3 = g_hist[i0 + 3] + 1;
    }
    int s0 = v0, s1 = s0 + v1, s2 = s1 + v2, s3 = s2 + v3;
    int tsum = s3;
    int incl = tsum;
    #pragma unroll
    for (int off = 1; off < 32; off <<= 1) {
        int n = __shfl_up_sync(0xffffffffu, incl, off);
        if (lane >= off) incl += n;
    }
    if (lane == 31) wsum[wid] = incl;
    __syncthreads();
    if (wid == 0 && lane < 8) {
        int wv = wsum[lane];
        int wi = wv;
        #pragma unroll
        for (int off = 1; off < 8; off <<= 1) {
            int n = __shfl_up_sync(0xffu, wi, off);
            if (lane >= off) wi += n;
        }
        wsum[lane] = wi - wv;
        if (lane == 7) blktot = wi;
    }
    __syncthreads();
    int base = wsum[wid] + (incl - tsum);
    if (i0 < N)     g_rowstart[i0]     = base;
    if (i0 + 1 < N) g_rowstart[i0 + 1] = base + s0;
    if (i0 + 2 < N) g_rowstart[i0 + 2] = base + s1;
    if (i0 + 3 < N) g_rowstart[i0 + 3] = base + s2;
    if (tid == 0) g_bsum[blockIdx.x] = blktot;
}

// ---------------- 3b) scan of block totals ----------------
__global__ void k_scanB(int nblk) {
    __shared__ int sp[MAXBLK];
    int tid = threadIdx.x;
    int v = (tid < nblk) ? g_bsum[tid] : 0;
    sp[tid] = v;
    __syncthreads();
    for (int off = 1; off < MAXBLK; off <<= 1) {
        int n = (tid >= off) ? sp[tid - off] : 0;
        __syncthreads();
        sp[tid] += n;
        __syncthreads();
    }
    if (tid < nblk) g_boff[tid] = sp[tid] - v;
}

// ---------------- 3c) apply block offsets ----------------
__global__ void k_scanC(int N, int totalEN) {
    int i = blockIdx.x * blockDim.x + threadIdx.x;
    if (i < N) {
        int r = g_rowstart[i] + g_boff[i >> 10];
        g_rowstart[i] = r;
        g_cursor[i]   = r;
    }
    if (i == 0) g_rowstart[N] = totalEN;
}

// ---------------- 4) scatter: group by dst + logits + segment max ----------------
__global__ void k_scatter(const void* __restrict__ ei, int N, int E) {
    int idx = blockIdx.x * blockDim.x + threadIdx.x;
    int is64 = g_is64;
    if (idx < E) {
        int d = edge_at(ei, E + idx, is64);
        int s = edge_at(ei, idx, is64);
        float e = g_asrc[s] + g_adst[d];
        e = (e >= 0.f) ? e : 0.2f * e;
        int pos = atomicAdd(&g_cursor[d], 1);
        g_edge[pos] = make_int2(s, __float_as_int(e));
        atomicMax(&g_maxkey[d], fkey(e));
    } else if (idx < E + N) {
        int i = idx - E;
        float e = g_asrc[i] + g_adst[i];
        e = (e >= 0.f) ? e : 0.2f * e;
        int pos = atomicAdd(&g_cursor[i], 1);
        g_edge[pos] = make_int2(i, __float_as_int(e));
        atomicMax(&g_maxkey[i], fkey(e));
    }
}

// ---------------- 5) fused softmax + gather: one WARP per dst node ----------------
__global__ void k_agg(const float* __restrict__ bias, float* __restrict__ out, int N) {
    const int gw = (blockIdx.x * blockDim.x + threadIdx.x) >> 5;
    const int lane = threadIdx.x & 31;
    if (gw >= N) return;

    const int beg = g_rowstart[gw];
    const int end = g_rowstart[gw + 1];
    const float m = funkey(g_maxkey[gw]);

    float4 acc = make_float4(0.f, 0.f, 0.f, 0.f);
    float sum = 0.f;

    for (int c = beg; c < end; c += 32) {
        int j = c + lane;
        int src = 0;
        float w = 0.f;
        if (j < end) {
            int2 ed = g_edge[j];
            src = ed.x;
            w = __expf(__int_as_float(ed.y) - m);
        }
        float ws = w;
        #pragma unroll
        for (int o = 16; o > 0; o >>= 1) ws += __shfl_xor_sync(0xffffffffu, ws, o);
        sum += ws;

        int cnt = min(32, end - c);
        if (cnt == 32) {
            #pragma unroll 8
            for (int jj = 0; jj < 32; ++jj) {
                float wj = __shfl_sync(0xffffffffu, w, jj);
                int   sj = __shfl_sync(0xffffffffu, src, jj);
                float4 v = ((const float4*)(g_xp + (size_t)sj * 128))[lane];
                acc.x += wj * v.x; acc.y += wj * v.y;
                acc.z += wj * v.z; acc.w += wj * v.w;
            }
        } else {
            for (int jj = 0; jj < cnt; ++jj) {
                float wj = __shfl_sync(0xffffffffu, w, jj);
                int   sj = __shfl_sync(0xffffffffu, src, jj);
                float4 v = ((const float4*)(g_xp + (size_t)sj * 128))[lane];
                acc.x += wj * v.x; acc.y += wj * v.y;
                acc.z += wj * v.z; acc.w += wj * v.w;
            }
        }
    }

    const float inv = 1.f / sum;
    float4 b4 = ((const float4*)bias)[lane];
    ((float4*)(out + (size_t)gw * 128))[lane] =
        make_float4(acc.x * inv + b4.x, acc.y * inv + b4.y,
                    acc.z * inv + b4.z, acc.w * inv + b4.w);
}

// ---------------- launch (fork-join: edge prep overlaps GEMM) ----------------
extern "C" void kernel_launch(void* const* d_in, const int* in_sizes, int n_in,
                              void* d_out, int out_size) {
    const float* x        = (const float*)d_in[0];
    const float* W        = (const float*)d_in[1];
    const float* att_src  = (const float*)d_in[2];
    const float* att_dst  = (const float*)d_in[3];
    const float* bias     = (const float*)d_in[4];
    const void*  ei       = d_in[5];

    const int N = in_sizes[0] / F;
    const int E = in_sizes[5] / 2;
    const int nblk = (N + SCAN_TILE - 1) / SCAN_TILE;
    float* out = (float*)d_out;

    static cudaStream_t s1 = nullptr;
    static cudaEvent_t e0 = nullptr, e1 = nullptr;
    static void* hist_addr = nullptr;
    if (s1 == nullptr) {
        cudaStreamCreateWithFlags(&s1, cudaStreamNonBlocking);
        cudaEventCreateWithFlags(&e0, cudaEventDisableTiming);
        cudaEventCreateWithFlags(&e1, cudaEventDisableTiming);
        cudaGetSymbolAddress(&hist_addr, g_hist);
    }

    // fork: s1 handles the edge-prep chain (independent of GEMM)
    cudaEventRecord(e0, 0);
    cudaStreamWaitEvent(s1, e0, 0);
    cudaMemsetAsync(hist_addr, 0, (size_t)N * sizeof(int), s1);
    k_detect <<<1, 256, 0, s1>>>((const int*)ei, E);
    k_hist   <<<(E + 1023) / 1024, 256, 0, s1>>>(ei, E);
    k_scanA  <<<nblk, 256, 0, s1>>>(N);
    k_scanB  <<<1, MAXBLK, 0, s1>>>(nblk);
    k_scanC  <<<(N + 255) / 256, 256, 0, s1>>>(N, E + N);
    cudaEventRecord(e1, s1);

    // main stream: W split + GEMM in parallel with the prep chain
    k_wsplit <<<64, 256>>>(W);
    k_gemm   <<<(N + 63) / 64, 256>>>(x, att_src, att_dst, N);

    // join, then edge scatter + aggregation
    cudaStreamWaitEvent(0, e1, 0);
    k_scatter<<<(E + N + 255) / 256, 256>>>(ei, N, E);
    k_agg    <<<(N + 7) / 8, 256>>>(bias, out, N);
}

// round 11
// speedup vs baseline: 2.7997x; 1.0808x over previous
#include <cuda_runtime.h>
#include <cuda_bf16.h>
#include <cstdint>

#define F 128
#define NMAX 65536
#define EMAX 1200000
#define SCAN_TILE 1024
#define MAXBLK (NMAX / SCAN_TILE)   // 64
#define XS2 136                     // bf16 stride; conflict-free A frags

// ---------------- scratch (no allocations allowed) ----------------
__device__ float          g_xp[NMAX * F];
__device__ float          g_asrc[NMAX];
__device__ float          g_adst[NMAX];
__device__ int            g_hist[NMAX];
__device__ int            g_rowstart[NMAX + 1];
__device__ int            g_cursor[NMAX];
__device__ int            g_bsum[MAXBLK];
__device__ int            g_flag[MAXBLK];
__device__ int            g_srcs[EMAX];      // src ids grouped by dst
__device__ int            g_is64;
__device__ __nv_bfloat16  g_whi[128 * 128];  // W^T split-hi, [n][k]
__device__ __nv_bfloat16  g_wlo[128 * 128];  // W^T split-lo, [n][k]

__device__ __forceinline__ int edge_at(const void* ei, int idx, int is64) {
    if (is64) return (int)((const long long*)ei)[idx];
    return ((const int*)ei)[idx];
}

__device__ __forceinline__ void mma_bf16(float* d, const uint32_t* a, const uint32_t* b) {
    asm volatile(
        "mma.sync.aligned.m16n8k16.row.col.f32.bf16.bf16.f32 "
        "{%0,%1,%2,%3}, {%4,%5,%6,%7}, {%8,%9}, {%0,%1,%2,%3};\n"
        : "+f"(d[0]), "+f"(d[1]), "+f"(d[2]), "+f"(d[3])
        : "r"(a[0]), "r"(a[1]), "r"(a[2]), "r"(a[3]), "r"(b[0]), "r"(b[1]));
}

// ---------------- 0) init: zero hist + flags, detect dtype (block 0) ----------------
__global__ void k_init(const int* __restrict__ ei32, int N, int E) {
    int i = blockIdx.x * blockDim.x + threadIdx.x;
    if (i < N) g_hist[i] = 0;
    if (i < MAXBLK) g_flag[i] = 0;
    if (blockIdx.x == 0) {
        __shared__ int any;
        if (threadIdx.x == 0) any = 0;
        __syncthreads();
        int total = 2 * E;
        int stride = (total / 2) / 4096;
        if (stride < 1) stride = 1;
        for (int q = threadIdx.x; q < 4096; q += blockDim.x) {
            long long w = 1 + 2 * (long long)q * stride;
            if (w < total && ei32[w] != 0) { any = 1; break; }
        }
        __syncthreads();
        if (threadIdx.x == 0) g_is64 = (any == 0) ? 1 : 0;
    }
}

// ---------------- 0b) split + transpose W -> bf16 hi/lo [n][k] ----------------
__global__ void k_wsplit(const float* __restrict__ W) {
    int idx = blockIdx.x * blockDim.x + threadIdx.x;   // 16384
    int k = idx >> 7, n = idx & 127;
    float a = W[idx];
    __nv_bfloat16 hi = __float2bfloat16_rn(a);
    __nv_bfloat16 lo = __float2bfloat16_rn(a - __bfloat162float(hi));
    g_whi[n * 128 + k] = hi;
    g_wlo[n * 128 + k] = lo;
}

// ---------------- 1) BF16 split tensor GEMM xp = x@W (+ fused attention logits) ----------------
__global__ void k_gemm(const float* __restrict__ x,
                       const float* __restrict__ att_src, const float* __restrict__ att_dst,
                       int N) {
    __shared__ __nv_bfloat16 xs_hi[64 * XS2];
    __shared__ __nv_bfloat16 xs_lo[64 * XS2];
    __shared__ float att_sh[256];
    __shared__ float sdot[128];

    const int tid  = threadIdx.x;               // 256
    const int lane = tid & 31;
    const int w    = tid >> 5;
    const int g    = lane >> 2;
    const int t    = lane & 3;
    const int warp_m = (w & 1) * 32;
    const int warp_n = (w >> 1) * 32;
    const int row0 = blockIdx.x * 64;

    if (tid < 128) {
        att_sh[tid]       = att_src[tid];
        att_sh[128 + tid] = att_dst[tid];
        sdot[tid] = 0.f;
    }

    {   // load + split x tile into bf16 hi/lo planes
        const float4* x4 = (const float4*)x;
        #pragma unroll
        for (int q = 0; q < 8; ++q) {
            int fi = q * 256 + tid;
            int r = fi >> 5, c4 = fi & 31;
            int gr = row0 + r;
            float4 v = make_float4(0.f, 0.f, 0.f, 0.f);
            if (gr < N) v = x4[gr * 32 + c4];
            __nv_bfloat16 h0 = __float2bfloat16_rn(v.x);
            __nv_bfloat16 h1 = __float2bfloat16_rn(v.y);
            __nv_bfloat16 h2 = __float2bfloat16_rn(v.z);
            __nv_bfloat16 h3 = __float2bfloat16_rn(v.w);
            __nv_bfloat16 l0 = __float2bfloat16_rn(v.x - __bfloat162float(h0));
            __nv_bfloat16 l1 = __float2bfloat16_rn(v.y - __bfloat162float(h1));
            __nv_bfloat16 l2 = __float2bfloat16_rn(v.z - __bfloat162float(h2));
            __nv_bfloat16 l3 = __float2bfloat16_rn(v.w - __bfloat162float(h3));
            int off = r * XS2 + c4 * 4;
            *(__nv_bfloat162*)&xs_hi[off]     = __nv_bfloat162(h0, h1);
            *(__nv_bfloat162*)&xs_hi[off + 2] = __nv_bfloat162(h2, h3);
            *(__nv_bfloat162*)&xs_lo[off]     = __nv_bfloat162(l0, l1);
            *(__nv_bfloat162*)&xs_lo[off + 2] = __nv_bfloat162(l2, l3);
        }
    }

    float acc[2][4][4];
    #pragma unroll
    for (int mi = 0; mi < 2; ++mi)
        #pragma unroll
        for (int ni = 0; ni < 4; ++ni)
            #pragma unroll
            for (int q = 0; q < 4; ++q) acc[mi][ni][q] = 0.f;

    __syncthreads();

    #pragma unroll
    for (int kt = 0; kt < 8; ++kt) {
        const int k0 = kt * 16 + 2 * t;
        uint32_t aHi[2][4], aLo[2][4];
        #pragma unroll
        for (int mi = 0; mi < 2; ++mi) {
            int r0 = warp_m + mi * 16 + g;
            aHi[mi][0] = *(const uint32_t*)&xs_hi[r0 * XS2 + k0];
            aHi[mi][1] = *(const uint32_t*)&xs_hi[(r0 + 8) * XS2 + k0];
            aHi[mi][2] = *(const uint32_t*)&xs_hi[r0 * XS2 + k0 + 8];
            aHi[mi][3] = *(const uint32_t*)&xs_hi[(r0 + 8) * XS2 + k0 + 8];
            aLo[mi][0] = *(const uint32_t*)&xs_lo[r0 * XS2 + k0];
            aLo[mi][1] = *(const uint32_t*)&xs_lo[(r0 + 8) * XS2 + k0];
            aLo[mi][2] = *(const uint32_t*)&xs_lo[r0 * XS2 + k0 + 8];
            aLo[mi][3] = *(const uint32_t*)&xs_lo[(r0 + 8) * XS2 + k0 + 8];
        }
        uint32_t bHi[4][2], bLo[4][2];
        #pragma unroll
        for (int ni = 0; ni < 4; ++ni) {
            int base = (warp_n + ni * 8 + g) * 128 + k0;
            bHi[ni][0] = *(const uint32_t*)&g_whi[base];
            bHi[ni][1] = *(const uint32_t*)&g_whi[base + 8];
            bLo[ni][0] = *(const uint32_t*)&g_wlo[base];
            bLo[ni][1] = *(const uint32_t*)&g_wlo[base + 8];
        }
        #pragma unroll
        for (int mi = 0; mi < 2; ++mi)
            #pragma unroll
            for (int ni = 0; ni < 4; ++ni) {
                mma_bf16(acc[mi][ni], aHi[mi], bHi[ni]);
                mma_bf16(acc[mi][ni], aLo[mi], bHi[ni]);
                mma_bf16(acc[mi][ni], aHi[mi], bLo[ni]);
            }
    }

    #pragma unroll
    for (int mi = 0; mi < 2; ++mi) {
        int gr = row0 + warp_m + mi * 16 + g;
        #pragma unroll
        for (int ni = 0; ni < 4; ++ni) {
            int col = warp_n + ni * 8 + 2 * t;
            if (gr < N)
                *(float2*)&g_xp[(size_t)gr * 128 + col] =
                    make_float2(acc[mi][ni][0], acc[mi][ni][1]);
            if (gr + 8 < N)
                *(float2*)&g_xp[(size_t)(gr + 8) * 128 + col] =
                    make_float2(acc[mi][ni][2], acc[mi][ni][3]);
        }
    }

    #pragma unroll
    for (int mi = 0; mi < 2; ++mi) {
        #pragma unroll
        for (int h = 0; h < 2; ++h) {
            float ds = 0.f, dd = 0.f;
            #pragma unroll
            for (int ni = 0; ni < 4; ++ni) {
                int col = warp_n + ni * 8 + 2 * t;
                float c0 = acc[mi][ni][h * 2 + 0];
                float c1 = acc[mi][ni][h * 2 + 1];
                ds += c0 * att_sh[col] + c1 * att_sh[col + 1];
                dd += c0 * att_sh[128 + col] + c1 * att_sh[128 + col + 1];
            }
            ds += __shfl_xor_sync(0xffffffffu, ds, 1);
            ds += __shfl_xor_sync(0xffffffffu, ds, 2);
            dd += __shfl_xor_sync(0xffffffffu, dd, 1);
            dd += __shfl_xor_sync(0xffffffffu, dd, 2);
            if (t == 0) {
                int rl = warp_m + mi * 16 + g + h * 8;
                atomicAdd(&sdot[rl], ds);
                atomicAdd(&sdot[64 + rl], dd);
            }
        }
    }
    __syncthreads();
    if (tid < 64) {
        int gr = row0 + tid;
        if (gr < N) {
            g_asrc[gr] = sdot[tid];
            g_adst[gr] = sdot[64 + tid];
        }
    }
}

// ---------------- 2) histogram of dst ----------------
__global__ void k_hist(const void* __restrict__ ei, int E) {
    int base = (blockIdx.x * blockDim.x + threadIdx.x) * 4;
    int is64 = g_is64;
    #pragma unroll
    for (int q = 0; q < 4; ++q) {
        int e = base + q;
        if (e < E) atomicAdd(&g_hist[edge_at(ei, E + e, is64)], 1);
    }
}

// ---------------- 3) single-pass scan with decoupled lookback ----------------
__global__ void k_scanF(int N, int totalEN) {
    __shared__ int wsum[8];
    __shared__ int blktot_sh;
    __shared__ int s_off;
    const int tid = threadIdx.x;
    const int bid = blockIdx.x;
    const int lane = tid & 31, wid = tid >> 5;
    const int i0 = bid * SCAN_TILE + tid * 4;

    int v0 = 0, v1 = 0, v2 = 0, v3 = 0;
    if (i0 + 3 < N) {
        int4 v = *(const int4*)&g_hist[i0];
        v0 = v.x + 1; v1 = v.y + 1; v2 = v.z + 1; v3 = v.w + 1;   // +1 self loop
    } else {
        if (i0 < N)     v0 = g_hist[i0] + 1;
        if (i0 + 1 < N) v1 = g_hist[i0 + 1] + 1;
        if (i0 + 2 < N) v2 = g_hist[i0 + 2] + 1;
        if (i0 + 3 < N) v3 = g_hist[i0 + 3] + 1;
    }
    int s0 = v0, s1 = s0 + v1, s2 = s1 + v2, s3 = s2 + v3;
    int tsum = s3;
    int incl = tsum;
    #pragma unroll
    for (int off = 1; off < 32; off <<= 1) {
        int n = __shfl_up_sync(0xffffffffu, incl, off);
        if (lane >= off) incl += n;
    }
    if (lane == 31) wsum[wid] = incl;
    if (tid == 0) s_off = 0;
    __syncthreads();
    if (wid == 0 && lane < 8) {
        int wv = wsum[lane];
        int wi = wv;
        #pragma unroll
        for (int off = 1; off < 8; off <<= 1) {
            int n = __shfl_up_sync(0xffu, wi, off);
            if (lane >= off) wi += n;
        }
        wsum[lane] = wi - wv;
        if (lane == 7) blktot_sh = wi;
    }
    __syncthreads();

    // publish aggregate, then sum predecessors' aggregates
    if (tid == 0) {
        g_bsum[bid] = blktot_sh;
        __threadfence();
        atomicExch(&g_flag[bid], 1);
    }
    if (tid < bid) {   // bid <= 48 < 256
        while (atomicAdd(&g_flag[tid], 0) == 0) { }
        atomicAdd(&s_off, atomicAdd(&g_bsum[tid], 0));
    }
    __syncthreads();
    const int goff = s_off;

    int base = goff + wsum[wid] + (incl - tsum);
    if (i0 < N)     { g_rowstart[i0]     = base;      g_cursor[i0]     = base; }
    if (i0 + 1 < N) { g_rowstart[i0 + 1] = base + s0; g_cursor[i0 + 1] = base + s0; }
    if (i0 + 2 < N) { g_rowstart[i0 + 2] = base + s1; g_cursor[i0 + 2] = base + s1; }
    if (i0 + 3 < N) { g_rowstart[i0 + 3] = base + s2; g_cursor[i0 + 3] = base + s2; }
    if (bid == 0 && tid == 0) g_rowstart[N] = totalEN;
}

// ---------------- 4) scatter: src ids grouped by dst (no logits needed) ----------------
__global__ void k_scatter1(const void* __restrict__ ei, int N, int E) {
    int idx = blockIdx.x * blockDim.x + threadIdx.x;
    int is64 = g_is64;
    if (idx < E) {
        int d = edge_at(ei, E + idx, is64);
        int s = edge_at(ei, idx, is64);
        int pos = atomicAdd(&g_cursor[d], 1);
        g_srcs[pos] = s;
    } else if (idx < E + N) {
        int i = idx - E;
        int pos = atomicAdd(&g_cursor[i], 1);
        g_srcs[pos] = i;   // self loop
    }
}

// ---------------- 5) fully fused softmax + gather: one WARP per dst node ----------------
// logit e_j = leaky(asrc[src_j] + adst[gw]) computed in-kernel (dst == gw)
__global__ void k_agg(const float* __restrict__ bias, float* __restrict__ out, int N) {
    const int gw = (blockIdx.x * blockDim.x + threadIdx.x) >> 5;
    const int lane = threadIdx.x & 31;
    if (gw >= N) return;

    const int beg = g_rowstart[gw];
    const int end = g_rowstart[gw + 1];
    const float adst = g_adst[gw];

    // pass 1: segment max
    float m = -3.4e38f;
    for (int c = beg; c < end; c += 32) {
        int j = c + lane;
        if (j < end) {
            float e = g_asrc[g_srcs[j]] + adst;
            e = (e >= 0.f) ? e : 0.2f * e;
            m = fmaxf(m, e);
        }
    }
    #pragma unroll
    for (int o = 16; o > 0; o >>= 1) m = fmaxf(m, __shfl_xor_sync(0xffffffffu, m, o));

    // pass 2: weights + gather
    float4 acc = make_float4(0.f, 0.f, 0.f, 0.f);
    float sum = 0.f;
    for (int c = beg; c < end; c += 32) {
        int j = c + lane;
        int src = 0;
        float w = 0.f;
        if (j < end) {
            src = g_srcs[j];
            float e = g_asrc[src] + adst;
            e = (e >= 0.f) ? e : 0.2f * e;
            w = __expf(e - m);
        }
        float ws = w;
        #pragma unroll
        for (int o = 16; o > 0; o >>= 1) ws += __shfl_xor_sync(0xffffffffu, ws, o);
        sum += ws;

        int cnt = min(32, end - c);
        if (cnt == 32) {
            #pragma unroll 8
            for (int jj = 0; jj < 32; ++jj) {
                float wj = __shfl_sync(0xffffffffu, w, jj);
                int   sj = __shfl_sync(0xffffffffu, src, jj);
                float4 v = ((const float4*)(g_xp + (size_t)sj * 128))[lane];
                acc.x += wj * v.x; acc.y += wj * v.y;
                acc.z += wj * v.z; acc.w += wj * v.w;
            }
        } else {
            for (int jj = 0; jj < cnt; ++jj) {
                float wj = __shfl_sync(0xffffffffu, w, jj);
                int   sj = __shfl_sync(0xffffffffu, src, jj);
                float4 v = ((const float4*)(g_xp + (size_t)sj * 128))[lane];
                acc.x += wj * v.x; acc.y += wj * v.y;
                acc.z += wj * v.z; acc.w += wj * v.w;
            }
        }
    }

    const float inv = 1.f / sum;
    float4 b4 = ((const float4*)bias)[lane];
    ((float4*)(out + (size_t)gw * 128))[lane] =
        make_float4(acc.x * inv + b4.x, acc.y * inv + b4.y,
                    acc.z * inv + b4.z, acc.w * inv + b4.w);
}

// ---------------- launch (fork-join: edge prep overlaps GEMM) ----------------
extern "C" void kernel_launch(void* const* d_in, const int* in_sizes, int n_in,
                              void* d_out, int out_size) {
    const float* x        = (const float*)d_in[0];
    const float* W        = (const float*)d_in[1];
    const float* att_src  = (const float*)d_in[2];
    const float* att_dst  = (const float*)d_in[3];
    const float* bias     = (const float*)d_in[4];
    const void*  ei       = d_in[5];

    const int N = in_sizes[0] / F;
    const int E = in_sizes[5] / 2;
    const int nblk = (N + SCAN_TILE - 1) / SCAN_TILE;
    float* out = (float*)d_out;

    static cudaStream_t s1 = nullptr;
    static cudaEvent_t e0 = nullptr, e1 = nullptr;
    if (s1 == nullptr) {
        cudaStreamCreateWithFlags(&s1, cudaStreamNonBlocking);
        cudaEventCreateWithFlags(&e0, cudaEventDisableTiming);
        cudaEventCreateWithFlags(&e1, cudaEventDisableTiming);
    }

    // fork: s1 handles the edge-prep chain (independent of GEMM)
    cudaEventRecord(e0, 0);
    cudaStreamWaitEvent(s1, e0, 0);
    k_init    <<<(N + 255) / 256, 256, 0, s1>>>((const int*)ei, N, E);
    k_hist    <<<(E + 1023) / 1024, 256, 0, s1>>>(ei, E);
    k_scanF   <<<nblk, 256, 0, s1>>>(N, E + N);
    k_scatter1<<<(E + N + 255) / 256, 256, 0, s1>>>(ei, N, E);
    cudaEventRecord(e1, s1);

    // main stream: W split + GEMM in parallel with the prep chain
    k_wsplit <<<64, 256>>>(W);
    k_gemm   <<<(N + 63) / 64, 256>>>(x, att_src, att_dst, N);

    // join, then fused softmax+aggregation
    cudaStreamWaitEvent(0, e1, 0);
    k_agg    <<<(N + 7) / 8, 256>>>(bias, out, N);
}

// round 12
// speedup vs baseline: 2.8768x; 1.0276x over previous
#include <cuda_runtime.h>
#include <cuda_bf16.h>
#include <cstdint>

#define F 128
#define NMAX 65536
#define EMAX 1200000
#define SCAN_TILE 1024
#define MAXBLK (NMAX / SCAN_TILE)   // 64
#define XS2 136                     // bf16 stride; conflict-free A frags

// ---------------- scratch (no allocations allowed) ----------------
__device__ float          g_xp[NMAX * F];
__device__ float          g_asrc[NMAX];
__device__ float          g_adst[NMAX];
__device__ int            g_hist[NMAX];
__device__ int            g_rowstart[NMAX + 1];
__device__ int            g_rank[EMAX];      // edge rank within its dst
__device__ int            g_bsum[MAXBLK];
__device__ int            g_flag[MAXBLK];
__device__ int            g_srcs[EMAX];      // src ids grouped by dst
__device__ int            g_is64;
__device__ __nv_bfloat16  g_whi[128 * 128];  // W^T split-hi, [n][k]
__device__ __nv_bfloat16  g_wlo[128 * 128];  // W^T split-lo, [n][k]

__device__ __forceinline__ int edge_at(const void* ei, int idx, int is64) {
    if (is64) return (int)((const long long*)ei)[idx];
    return ((const int*)ei)[idx];
}

__device__ __forceinline__ void mma_bf16(float* d, const uint32_t* a, const uint32_t* b) {
    asm volatile(
        "mma.sync.aligned.m16n8k16.row.col.f32.bf16.bf16.f32 "
        "{%0,%1,%2,%3}, {%4,%5,%6,%7}, {%8,%9}, {%0,%1,%2,%3};\n"
        : "+f"(d[0]), "+f"(d[1]), "+f"(d[2]), "+f"(d[3])
        : "r"(a[0]), "r"(a[1]), "r"(a[2]), "r"(a[3]), "r"(b[0]), "r"(b[1]));
}

// ---------------- 0) init: zero hist + flags, detect dtype (block 0) ----------------
__global__ void k_init(const int* __restrict__ ei32, int N, int E) {
    int i = blockIdx.x * blockDim.x + threadIdx.x;
    if (i < N) g_hist[i] = 0;
    if (i < MAXBLK) g_flag[i] = 0;
    if (blockIdx.x == 0) {
        __shared__ int any;
        if (threadIdx.x == 0) any = 0;
        __syncthreads();
        int total = 2 * E;
        int stride = (total / 2) / 4096;
        if (stride < 1) stride = 1;
        for (int q = threadIdx.x; q < 4096; q += blockDim.x) {
            long long w = 1 + 2 * (long long)q * stride;
            if (w < total && ei32[w] != 0) { any = 1; break; }
        }
        __syncthreads();
        if (threadIdx.x == 0) g_is64 = (any == 0) ? 1 : 0;
    }
}

// ---------------- 0b) split + transpose W -> bf16 hi/lo [n][k] ----------------
__global__ void k_wsplit(const float* __restrict__ W) {
    int idx = blockIdx.x * blockDim.x + threadIdx.x;   // 16384
    int k = idx >> 7, n = idx & 127;
    float a = W[idx];
    __nv_bfloat16 hi = __float2bfloat16_rn(a);
    __nv_bfloat16 lo = __float2bfloat16_rn(a - __bfloat162float(hi));
    g_whi[n * 128 + k] = hi;
    g_wlo[n * 128 + k] = lo;
}

// ---------------- 1) BF16 split tensor GEMM xp = x@W (+ fused attention logits) ----------------
__global__ void k_gemm(const float* __restrict__ x,
                       const float* __restrict__ att_src, const float* __restrict__ att_dst,
                       int N) {
    __shared__ __nv_bfloat16 xs_hi[64 * XS2];
    __shared__ __nv_bfloat16 xs_lo[64 * XS2];
    __shared__ float att_sh[256];
    __shared__ float sdot[128];

    const int tid  = threadIdx.x;               // 256
    const int lane = tid & 31;
    const int w    = tid >> 5;
    const int g    = lane >> 2;
    const int t    = lane & 3;
    const int warp_m = (w & 1) * 32;
    const int warp_n = (w >> 1) * 32;
    const int row0 = blockIdx.x * 64;

    if (tid < 128) {
        att_sh[tid]       = att_src[tid];
        att_sh[128 + tid] = att_dst[tid];
        sdot[tid] = 0.f;
    }

    {   // load + split x tile into bf16 hi/lo planes
        const float4* x4 = (const float4*)x;
        #pragma unroll
        for (int q = 0; q < 8; ++q) {
            int fi = q * 256 + tid;
            int r = fi >> 5, c4 = fi & 31;
            int gr = row0 + r;
            float4 v = make_float4(0.f, 0.f, 0.f, 0.f);
            if (gr < N) v = x4[gr * 32 + c4];
            __nv_bfloat16 h0 = __float2bfloat16_rn(v.x);
            __nv_bfloat16 h1 = __float2bfloat16_rn(v.y);
            __nv_bfloat16 h2 = __float2bfloat16_rn(v.z);
            __nv_bfloat16 h3 = __float2bfloat16_rn(v.w);
            __nv_bfloat16 l0 = __float2bfloat16_rn(v.x - __bfloat162float(h0));
            __nv_bfloat16 l1 = __float2bfloat16_rn(v.y - __bfloat162float(h1));
            __nv_bfloat16 l2 = __float2bfloat16_rn(v.z - __bfloat162float(h2));
            __nv_bfloat16 l3 = __float2bfloat16_rn(v.w - __bfloat162float(h3));
            int off = r * XS2 + c4 * 4;
            *(__nv_bfloat162*)&xs_hi[off]     = __nv_bfloat162(h0, h1);
            *(__nv_bfloat162*)&xs_hi[off + 2] = __nv_bfloat162(h2, h3);
            *(__nv_bfloat162*)&xs_lo[off]     = __nv_bfloat162(l0, l1);
            *(__nv_bfloat162*)&xs_lo[off + 2] = __nv_bfloat162(l2, l3);
        }
    }

    float acc[2][4][4];
    #pragma unroll
    for (int mi = 0; mi < 2; ++mi)
        #pragma unroll
        for (int ni = 0; ni < 4; ++ni)
            #pragma unroll
            for (int q = 0; q < 4; ++q) acc[mi][ni][q] = 0.f;

    __syncthreads();

    #pragma unroll
    for (int kt = 0; kt < 8; ++kt) {
        const int k0 = kt * 16 + 2 * t;
        uint32_t aHi[2][4], aLo[2][4];
        #pragma unroll
        for (int mi = 0; mi < 2; ++mi) {
            int r0 = warp_m + mi * 16 + g;
            aHi[mi][0] = *(const uint32_t*)&xs_hi[r0 * XS2 + k0];
            aHi[mi][1] = *(const uint32_t*)&xs_hi[(r0 + 8) * XS2 + k0];
            aHi[mi][2] = *(const uint32_t*)&xs_hi[r0 * XS2 + k0 + 8];
            aHi[mi][3] = *(const uint32_t*)&xs_hi[(r0 + 8) * XS2 + k0 + 8];
            aLo[mi][0] = *(const uint32_t*)&xs_lo[r0 * XS2 + k0];
            aLo[mi][1] = *(const uint32_t*)&xs_lo[(r0 + 8) * XS2 + k0];
            aLo[mi][2] = *(const uint32_t*)&xs_lo[r0 * XS2 + k0 + 8];
            aLo[mi][3] = *(const uint32_t*)&xs_lo[(r0 + 8) * XS2 + k0 + 8];
        }
        uint32_t bHi[4][2], bLo[4][2];
        #pragma unroll
        for (int ni = 0; ni < 4; ++ni) {
            int base = (warp_n + ni * 8 + g) * 128 + k0;
            bHi[ni][0] = *(const uint32_t*)&g_whi[base];
            bHi[ni][1] = *(const uint32_t*)&g_whi[base + 8];
            bLo[ni][0] = *(const uint32_t*)&g_wlo[base];
            bLo[ni][1] = *(const uint32_t*)&g_wlo[base + 8];
        }
        #pragma unroll
        for (int mi = 0; mi < 2; ++mi)
            #pragma unroll
            for (int ni = 0; ni < 4; ++ni) {
                mma_bf16(acc[mi][ni], aHi[mi], bHi[ni]);
                mma_bf16(acc[mi][ni], aLo[mi], bHi[ni]);
                mma_bf16(acc[mi][ni], aHi[mi], bLo[ni]);
            }
    }

    #pragma unroll
    for (int mi = 0; mi < 2; ++mi) {
        int gr = row0 + warp_m + mi * 16 + g;
        #pragma unroll
        for (int ni = 0; ni < 4; ++ni) {
            int col = warp_n + ni * 8 + 2 * t;
            if (gr < N)
                *(float2*)&g_xp[(size_t)gr * 128 + col] =
                    make_float2(acc[mi][ni][0], acc[mi][ni][1]);
            if (gr + 8 < N)
                *(float2*)&g_xp[(size_t)(gr + 8) * 128 + col] =
                    make_float2(acc[mi][ni][2], acc[mi][ni][3]);
        }
    }

    #pragma unroll
    for (int mi = 0; mi < 2; ++mi) {
        #pragma unroll
        for (int h = 0; h < 2; ++h) {
            float ds = 0.f, dd = 0.f;
            #pragma unroll
            for (int ni = 0; ni < 4; ++ni) {
                int col = warp_n + ni * 8 + 2 * t;
                float c0 = acc[mi][ni][h * 2 + 0];
                float c1 = acc[mi][ni][h * 2 + 1];
                ds += c0 * att_sh[col] + c1 * att_sh[col + 1];
                dd += c0 * att_sh[128 + col] + c1 * att_sh[128 + col + 1];
            }
            ds += __shfl_xor_sync(0xffffffffu, ds, 1);
            ds += __shfl_xor_sync(0xffffffffu, ds, 2);
            dd += __shfl_xor_sync(0xffffffffu, dd, 1);
            dd += __shfl_xor_sync(0xffffffffu, dd, 2);
            if (t == 0) {
                int rl = warp_m + mi * 16 + g + h * 8;
                atomicAdd(&sdot[rl], ds);
                atomicAdd(&sdot[64 + rl], dd);
            }
        }
    }
    __syncthreads();
    if (tid < 64) {
        int gr = row0 + tid;
        if (gr < N) {
            g_asrc[gr] = sdot[tid];
            g_adst[gr] = sdot[64 + tid];
        }
    }
}

// ---------------- 2) histogram of dst + per-edge rank ----------------
__global__ void k_hist(const void* __restrict__ ei, int E) {
    int base = (blockIdx.x * blockDim.x + threadIdx.x) * 4;
    int is64 = g_is64;
    #pragma unroll
    for (int q = 0; q < 4; ++q) {
        int e = base + q;
        if (e < E) {
            int d = edge_at(ei, E + e, is64);
            g_rank[e] = atomicAdd(&g_hist[d], 1);
        }
    }
}

// ---------------- 3) single-pass scan with decoupled lookback ----------------
__global__ void k_scanF(int N, int totalEN) {
    __shared__ int wsum[8];
    __shared__ int blktot_sh;
    __shared__ int s_off;
    const int tid = threadIdx.x;
    const int bid = blockIdx.x;
    const int lane = tid & 31, wid = tid >> 5;
    const int i0 = bid * SCAN_TILE + tid * 4;

    int v0 = 0, v1 = 0, v2 = 0, v3 = 0;
    if (i0 + 3 < N) {
        int4 v = *(const int4*)&g_hist[i0];
        v0 = v.x + 1; v1 = v.y + 1; v2 = v.z + 1; v3 = v.w + 1;   // +1 self loop
    } else {
        if (i0 < N)     v0 = g_hist[i0] + 1;
        if (i0 + 1 < N) v1 = g_hist[i0 + 1] + 1;
        if (i0 + 2 < N) v2 = g_hist[i0 + 2] + 1;
        if (i0 + 3 < N) v3 = g_hist[i0 + 3] + 1;
    }
    int s0 = v0, s1 = s0 + v1, s2 = s1 + v2, s3 = s2 + v3;
    int tsum = s3;
    int incl = tsum;
    #pragma unroll
    for (int off = 1; off < 32; off <<= 1) {
        int n = __shfl_up_sync(0xffffffffu, incl, off);
        if (lane >= off) incl += n;
    }
    if (lane == 31) wsum[wid] = incl;
    if (tid == 0) s_off = 0;
    __syncthreads();
    if (wid == 0 && lane < 8) {
        int wv = wsum[lane];
        int wi = wv;
        #pragma unroll
        for (int off = 1; off < 8; off <<= 1) {
            int n = __shfl_up_sync(0xffu, wi, off);
            if (lane >= off) wi += n;
        }
        wsum[lane] = wi - wv;
        if (lane == 7) blktot_sh = wi;
    }
    __syncthreads();

    if (tid == 0) {
        g_bsum[bid] = blktot_sh;
        __threadfence();
        atomicExch(&g_flag[bid], 1);
    }
    if (tid < bid) {   // bid <= 48 < 256
        while (atomicAdd(&g_flag[tid], 0) == 0) { }
        atomicAdd(&s_off, atomicAdd(&g_bsum[tid], 0));
    }
    __syncthreads();
    const int goff = s_off;

    int base = goff + wsum[wid] + (incl - tsum);
    if (i0 < N)     g_rowstart[i0]     = base;
    if (i0 + 1 < N) g_rowstart[i0 + 1] = base + s0;
    if (i0 + 2 < N) g_rowstart[i0 + 2] = base + s1;
    if (i0 + 3 < N) g_rowstart[i0 + 3] = base + s2;
    if (bid == 0 && tid == 0) g_rowstart[N] = totalEN;
}

// ---------------- 4) scatter (atomic-free): srcs[rowstart[d] + rank] = s ----------------
__global__ void k_scatter1(const void* __restrict__ ei, int N, int E) {
    int idx = blockIdx.x * blockDim.x + threadIdx.x;
    int is64 = g_is64;
    if (idx < E) {
        int d = edge_at(ei, E + idx, is64);
        int s = edge_at(ei, idx, is64);
        g_srcs[g_rowstart[d] + g_rank[idx]] = s;
    } else if (idx < E + N) {
        int i = idx - E;
        g_srcs[g_rowstart[i + 1] - 1] = i;   // self loop takes the last slot
    }
}

// ---------------- 5) online-softmax fused gather: one WARP per dst node ----------------
__global__ void k_agg(const float* __restrict__ bias, float* __restrict__ out, int N) {
    const int gw = (blockIdx.x * blockDim.x + threadIdx.x) >> 5;
    const int lane = threadIdx.x & 31;
    if (gw >= N) return;

    const int beg = g_rowstart[gw];
    const int end = g_rowstart[gw + 1];
    const float adst = g_adst[gw];

    float m = -3.4e38f;
    float sum = 0.f;
    float4 acc = make_float4(0.f, 0.f, 0.f, 0.f);

    for (int c = beg; c < end; c += 32) {
        int j = c + lane;
        int src = 0;
        float e = -3.4e38f;
        if (j < end) {
            src = g_srcs[j];
            e = g_asrc[src] + adst;
            e = (e >= 0.f) ? e : 0.2f * e;
        }
        // chunk max + online rescale
        float cm = e;
        #pragma unroll
        for (int o = 16; o > 0; o >>= 1) cm = fmaxf(cm, __shfl_xor_sync(0xffffffffu, cm, o));
        float m_new = fmaxf(m, cm);
        float scale = __expf(m - m_new);     // 0 on first chunk
        m = m_new;
        sum *= scale;
        acc.x *= scale; acc.y *= scale; acc.z *= scale; acc.w *= scale;

        float w = (j < end) ? __expf(e - m) : 0.f;
        float ws = w;
        #pragma unroll
        for (int o = 16; o > 0; o >>= 1) ws += __shfl_xor_sync(0xffffffffu, ws, o);
        sum += ws;

        int cnt = min(32, end - c);
        if (cnt == 32) {
            #pragma unroll 8
            for (int jj = 0; jj < 32; ++jj) {
                float wj = __shfl_sync(0xffffffffu, w, jj);
                int   sj = __shfl_sync(0xffffffffu, src, jj);
                float4 v = ((const float4*)(g_xp + (size_t)sj * 128))[lane];
                acc.x += wj * v.x; acc.y += wj * v.y;
                acc.z += wj * v.z; acc.w += wj * v.w;
            }
        } else {
            for (int jj = 0; jj < cnt; ++jj) {
                float wj = __shfl_sync(0xffffffffu, w, jj);
                int   sj = __shfl_sync(0xffffffffu, src, jj);
                float4 v = ((const float4*)(g_xp + (size_t)sj * 128))[lane];
                acc.x += wj * v.x; acc.y += wj * v.y;
                acc.z += wj * v.z; acc.w += wj * v.w;
            }
        }
    }

    const float inv = 1.f / sum;
    float4 b4 = ((const float4*)bias)[lane];
    ((float4*)(out + (size_t)gw * 128))[lane] =
        make_float4(acc.x * inv + b4.x, acc.y * inv + b4.y,
                    acc.z * inv + b4.z, acc.w * inv + b4.w);
}

// ---------------- launch (fork-join: edge prep overlaps GEMM) ----------------
extern "C" void kernel_launch(void* const* d_in, const int* in_sizes, int n_in,
                              void* d_out, int out_size) {
    const float* x        = (const float*)d_in[0];
    const float* W        = (const float*)d_in[1];
    const float* att_src  = (const float*)d_in[2];
    const float* att_dst  = (const float*)d_in[3];
    const float* bias     = (const float*)d_in[4];
    const void*  ei       = d_in[5];

    const int N = in_sizes[0] / F;
    const int E = in_sizes[5] / 2;
    const int nblk = (N + SCAN_TILE - 1) / SCAN_TILE;
    float* out = (float*)d_out;

    static cudaStream_t s1 = nullptr;
    static cudaEvent_t e0 = nullptr, e1 = nullptr;
    if (s1 == nullptr) {
        cudaStreamCreateWithFlags(&s1, cudaStreamNonBlocking);
        cudaEventCreateWithFlags(&e0, cudaEventDisableTiming);
        cudaEventCreateWithFlags(&e1, cudaEventDisableTiming);
    }

    // fork: s1 handles the edge-prep chain (independent of GEMM)
    cudaEventRecord(e0, 0);
    cudaStreamWaitEvent(s1, e0, 0);
    k_init    <<<(N + 255) / 256, 256, 0, s1>>>((const int*)ei, N, E);
    k_hist    <<<(E + 1023) / 1024, 256, 0, s1>>>(ei, E);
    k_scanF   <<<nblk, 256, 0, s1>>>(N, E + N);
    k_scatter1<<<(E + N + 255) / 256, 256, 0, s1>>>(ei, N, E);
    cudaEventRecord(e1, s1);

    // main stream: W split + GEMM in parallel with the prep chain
    k_wsplit <<<64, 256>>>(W);
    k_gemm   <<<(N + 63) / 64, 256>>>(x, att_src, att_dst, N);

    // join, then fused online-softmax aggregation
    cudaStreamWaitEvent(0, e1, 0);
    k_agg    <<<(N + 7) / 8, 256>>>(bias, out, N);
}